// round 10
// baseline (speedup 1.0000x reference)
#include <cuda_runtime.h>
#include <cuda_bf16.h>
#include <math.h>

#define BB 32
#define SS 512
#define TT 50
#define LL 562      // S+T
#define DD 512
#define HH 8
#define FFDIM 2048
#define NLAYER 4
#define VBB 30000
#define BLROWS (BB*LL)   // 17984
#define KSPLIT 75
#define KCHUNK 400

// weight-conversion buffer offsets (floats)
#define WQ_OFF 0
#define WK_OFF 1048576
#define WV_OFF 2097152
#define WO_OFF 3145728
#define WI_OFF 4194304
#define WF_OFF 8388608
#define W2_OFF 12582912
#define WCONV_TOTAL 13107200

// ---------------- scratch ----------------
__device__ float g_wd[TT*VBB];
__device__ float g_part[KSPLIT*TT*1024];
__device__ float g_hmem[TT*1024];
__device__ float g_topic[TT*DD];
__device__ float g_q[BLROWS*DD];
__device__ float g_k[BLROWS*DD];
__device__ float g_v[BLROWS*DD];
__device__ float g_ctx[BLROWS*DD];
__device__ float g_t[BLROWS*DD];
__device__ float g_ff[(size_t)BLROWS*FFDIM];
__device__ float g_hconv[BLROWS*DD];
__device__ float g_wconv[WCONV_TOTAL];

// ---------------- helpers ----------------
__device__ __forceinline__ float warp_red_sum(float v){
    #pragma unroll
    for (int o=16;o>0;o>>=1) v += __shfl_xor_sync(0xffffffffu, v, o);
    return v;
}
__device__ __forceinline__ float warp_red_max(float v){
    #pragma unroll
    for (int o=16;o>0;o>>=1) v = fmaxf(v, __shfl_xor_sync(0xffffffffu, v, o));
    return v;
}
__device__ __forceinline__ unsigned f2tf32(float x){
    unsigned r;
    asm("cvt.rna.tf32.f32 %0, %1;" : "=r"(r) : "f"(x));
    return r;
}
__device__ __forceinline__ float rnd_tf32(float x){ return __uint_as_float(f2tf32(x)); }
__device__ __forceinline__ void mma_tf32(float* d, const unsigned* a, unsigned b0, unsigned b1){
    asm volatile(
        "mma.sync.aligned.m16n8k8.row.col.f32.tf32.tf32.f32 "
        "{%0,%1,%2,%3}, {%4,%5,%6,%7}, {%8,%9}, {%0,%1,%2,%3};"
        : "+f"(d[0]), "+f"(d[1]), "+f"(d[2]), "+f"(d[3])
        : "r"(a[0]), "r"(a[1]), "r"(a[2]), "r"(a[3]), "r"(b0), "r"(b1));
}

// tf32-round a tensor (float4 vectorized)
__global__ void k_conv(const float* __restrict__ src, float* __restrict__ dst, int n4){
    int i = blockIdx.x*256 + threadIdx.x;
    if (i >= n4) return;
    float4 v = ((const float4*)src)[i];
    uint4 t; t.x=f2tf32(v.x); t.y=f2tf32(v.y); t.z=f2tf32(v.z); t.w=f2tf32(v.w);
    ((uint4*)dst)[i] = t;
}

// ---------------- topic memory pipeline ----------------
__global__ void k_wdec_softmax(const float* __restrict__ W, const float* __restrict__ bvec){
    int row = blockIdx.x, tid = threadIdx.x;
    __shared__ float red[32];
    const float* w = W + (size_t)row*VBB;
    float m = -1e30f;
    for (int i=tid;i<VBB;i+=1024) m = fmaxf(m, w[i]+bvec[i]);
    m = warp_red_max(m);
    if ((tid&31)==0) red[tid>>5]=m;
    __syncthreads();
    float mm = red[0];
    #pragma unroll
    for (int i=1;i<32;i++) mm = fmaxf(mm, red[i]);
    float s = 0.f;
    for (int i=tid;i<VBB;i+=1024) s += __expf(w[i]+bvec[i]-mm);
    s = warp_red_sum(s);
    __syncthreads();
    if ((tid&31)==0) red[tid>>5]=s;
    __syncthreads();
    float ss = 0.f;
    #pragma unroll
    for (int i=0;i<32;i++) ss += red[i];
    float inv = 1.0f/ss;
    for (int i=tid;i<VBB;i+=1024) g_wd[(size_t)row*VBB+i] = __expf(w[i]+bvec[i]-mm)*inv;
}

__global__ void k_mem_gemm1(const float* __restrict__ W1){
    __shared__ float wds[16][52];
    __shared__ float Ws[16][128];
    int n0 = blockIdx.x*128;
    int k0 = blockIdx.y*KCHUNK;
    int tid = threadIdx.x;
    int n = tid & 127, mb = (tid>>7)*25;
    float acc[25];
    #pragma unroll
    for (int i=0;i<25;i++) acc[i]=0.f;
    for (int kt=0; kt<KCHUNK; kt+=16){
        int kb = k0+kt;
        for (int x=tid;x<800;x+=256){ int m=x>>4, kk=x&15; wds[kk][m]=g_wd[(size_t)m*VBB + kb + kk]; }
        #pragma unroll
        for (int jj=0;jj<2;jj++){
            int idx = tid + jj*256;
            int r = idx>>5, c4 = (idx&31)*4;
            *(float4*)&Ws[r][c4] = *(const float4*)(W1 + (size_t)(kb+r)*1024 + n0 + c4);
        }
        __syncthreads();
        #pragma unroll
        for (int kk=0;kk<16;kk++){
            float w = Ws[kk][n];
            #pragma unroll
            for (int i=0;i<25;i++) acc[i] += wds[kk][mb+i]*w;
        }
        __syncthreads();
    }
    float* out = g_part + (size_t)blockIdx.y*(TT*1024);
    #pragma unroll
    for (int i=0;i<25;i++) out[(mb+i)*1024 + n0 + n] = acc[i];
}

__global__ void k_mem_reduce(const float* __restrict__ b1){
    int i = blockIdx.x*256 + threadIdx.x;
    if (i >= TT*1024) return;
    float s = 0.f;
    for (int ks=0; ks<KSPLIT; ks++) s += g_part[(size_t)ks*(TT*1024) + i];
    s += b1[i & 1023];
    g_hmem[i] = rnd_tf32(fmaxf(s, 0.f));
}

// LN over g_t[50,512] -> g_topic
__global__ __launch_bounds__(512)
void k_ln_topic(const float* __restrict__ src,
                const float* __restrict__ gg, const float* __restrict__ bbv){
    __shared__ float red[16];
    int row = blockIdx.x, tid = threadIdx.x;
    float a = src[row*512+tid];
    float s = warp_red_sum(a);
    if ((tid&31)==0) red[tid>>5]=s;
    __syncthreads();
    float tot=0.f;
    #pragma unroll
    for (int i=0;i<16;i++) tot+=red[i];
    float mean = tot*(1.f/512.f);
    float d = a-mean;
    float q = warp_red_sum(d*d);
    __syncthreads();
    if ((tid&31)==0) red[tid>>5]=q;
    __syncthreads();
    float vq=0.f;
    #pragma unroll
    for (int i=0;i<16;i++) vq+=red[i];
    float inv = rsqrtf(vq*(1.f/512.f) + 1e-12f);
    g_topic[row*512+tid] = d*inv*gg[tid] + bbv[tid];
}

// build hidden into d_out + tf32 copy into g_hconv
__global__ void k_build_hidden(const int* __restrict__ ids, const int* __restrict__ lens_p,
                               const float* __restrict__ embed, float* __restrict__ hid){
    int r = blockIdx.x;
    int b = r / LL, j = r % LL;
    int len = lens_p[b]; len = min(max(len,1),SS);
    const float* src;
    if (j >= len && j < len+TT){
        src = g_topic + (size_t)(j-len)*DD;
    } else {
        int sj = (j < len) ? j : (j - TT);
        sj = min(max(sj,0), SS-1);
        src = embed + (size_t)ids[b*SS + sj]*DD;
    }
    float4 v = ((const float4*)src)[threadIdx.x];
    ((float4*)(hid + (size_t)r*DD))[threadIdx.x] = v;
    uint4 t; t.x=f2tf32(v.x); t.y=f2tf32(v.y); t.z=f2tf32(v.z); t.w=f2tf32(v.w);
    ((uint4*)(g_hconv + (size_t)r*DD))[threadIdx.x] = t;
}

// ---------------- TF32 GEMM: cp.async 2-stage, 2 CTAs/SM, n-fast rasterization ----------------
// operands must already be tf32-rounded.
// ACT: 0 = plain, 1 = gelu + tf32-round output, 2 = tf32-round output
#define AS_F (128*36)            // 4608 floats
#define WS_F (32*136)            // 4352 floats
#define STG_F (AS_F + WS_F)      // 8960 floats = 35840 B / stage
#define GEMM_SMEM (2*STG_F*4)    // 71680 B

template<int ACT>
__device__ __forceinline__
void gemm_cp_body(const float* __restrict__ A, const float* __restrict__ W,
                  const float* __restrict__ bias, float* __restrict__ C,
                  int M, int N, int K, int m0, int n0)
{
    extern __shared__ float sm_[];
    const int tid = threadIdx.x;
    const int lane = tid & 31, warp = tid >> 5;
    const int wm = warp >> 2, wn = warp & 3;
    const int q = lane & 3, g = lane >> 2;

    float acc[4][4][4];
    #pragma unroll
    for (int a=0;a<4;a++)
        #pragma unroll
        for (int b=0;b<4;b++)
            #pragma unroll
            for (int c=0;c<4;c++) acc[a][b][c]=0.f;

    const int am = tid>>3, akv = tid&7;           // A: row am, 16B chunk akv
    const int wk = tid>>5, wnv = tid&31;          // W: row wk, 16B chunk wnv

    { // issue stage 0
        float* As = sm_;
        float* Ws = sm_ + AS_F;
        #pragma unroll
        for (int i=0;i<4;i++){
            int m = am + i*32;
            unsigned dst = (unsigned)__cvta_generic_to_shared(&As[m*36 + akv*4]);
            const float* src = A + (size_t)(m0+m)*K + akv*4;
            int sz = (m0+m < M) ? 16 : 0;
            asm volatile("cp.async.ca.shared.global [%0],[%1],16,%2;\n" :: "r"(dst), "l"(src), "r"(sz));
        }
        #pragma unroll
        for (int i=0;i<4;i++){
            int kk = wk + i*8;
            unsigned dst = (unsigned)__cvta_generic_to_shared(&Ws[kk*136 + wnv*4]);
            const float* src = W + (size_t)kk*N + n0 + wnv*4;
            asm volatile("cp.async.ca.shared.global [%0],[%1],16;\n" :: "r"(dst), "l"(src));
        }
        asm volatile("cp.async.commit_group;\n");
    }

    const int nk = K >> 5;
    for (int kt = 0; kt < nk; kt++){
        asm volatile("cp.async.wait_group 0;\n");
        __syncthreads();
        if (kt+1 < nk){
            int k0 = (kt+1)*32;
            float* As = sm_ + ((kt+1)&1)*STG_F;
            float* Ws = As + AS_F;
            #pragma unroll
            for (int i=0;i<4;i++){
                int m = am + i*32;
                unsigned dst = (unsigned)__cvta_generic_to_shared(&As[m*36 + akv*4]);
                const float* src = A + (size_t)(m0+m)*K + k0 + akv*4;
                int sz = (m0+m < M) ? 16 : 0;
                asm volatile("cp.async.ca.shared.global [%0],[%1],16,%2;\n" :: "r"(dst), "l"(src), "r"(sz));
            }
            #pragma unroll
            for (int i=0;i<4;i++){
                int kk = wk + i*8;
                unsigned dst = (unsigned)__cvta_generic_to_shared(&Ws[kk*136 + wnv*4]);
                const float* src = W + (size_t)(k0+kk)*N + n0 + wnv*4;
                asm volatile("cp.async.ca.shared.global [%0],[%1],16;\n" :: "r"(dst), "l"(src));
            }
            asm volatile("cp.async.commit_group;\n");
        }
        const float* As = sm_ + (kt&1)*STG_F;
        const float* Ws = As + AS_F;
        #pragma unroll
        for (int k8=0;k8<4;k8++){
            unsigned af[4][4], bf[4][2];
            #pragma unroll
            for (int mi=0;mi<4;mi++){
                int mr = wm*64 + mi*16 + g;
                af[mi][0] = __float_as_uint(As[mr*36     + k8*8+q  ]);
                af[mi][1] = __float_as_uint(As[(mr+8)*36 + k8*8+q  ]);
                af[mi][2] = __float_as_uint(As[mr*36     + k8*8+q+4]);
                af[mi][3] = __float_as_uint(As[(mr+8)*36 + k8*8+q+4]);
            }
            #pragma unroll
            for (int nj=0;nj<4;nj++){
                int nc = wn*32 + nj*8 + g;
                bf[nj][0] = __float_as_uint(Ws[(k8*8+q  )*136 + nc]);
                bf[nj][1] = __float_as_uint(Ws[(k8*8+q+4)*136 + nc]);
            }
            #pragma unroll
            for (int mi=0;mi<4;mi++)
                #pragma unroll
                for (int nj=0;nj<4;nj++)
                    mma_tf32(acc[mi][nj], af[mi], bf[nj][0], bf[nj][1]);
        }
    }

    #pragma unroll
    for (int nj=0;nj<4;nj++){
        int c0 = n0 + wn*32 + nj*8 + q*2;
        float bv0 = bias[c0], bv1 = bias[c0+1];
        #pragma unroll
        for (int mi=0;mi<4;mi++){
            int r0 = m0 + wm*64 + mi*16 + g;
            float v0 = acc[mi][nj][0] + bv0;
            float v1 = acc[mi][nj][1] + bv1;
            float v2 = acc[mi][nj][2] + bv0;
            float v3 = acc[mi][nj][3] + bv1;
            if (ACT==1){
                v0 = rnd_tf32(0.5f*v0*(1.0f+erff(v0*0.70710678118654752f)));
                v1 = rnd_tf32(0.5f*v1*(1.0f+erff(v1*0.70710678118654752f)));
                v2 = rnd_tf32(0.5f*v2*(1.0f+erff(v2*0.70710678118654752f)));
                v3 = rnd_tf32(0.5f*v3*(1.0f+erff(v3*0.70710678118654752f)));
            }
            if (ACT==2){
                v0 = rnd_tf32(v0); v1 = rnd_tf32(v1);
                v2 = rnd_tf32(v2); v3 = rnd_tf32(v3);
            }
            if (r0 < M)   { *(float2*)(C + (size_t)r0*N + c0) = make_float2(v0,v1); }
            if (r0+8 < M) { *(float2*)(C + (size_t)(r0+8)*N + c0) = make_float2(v2,v3); }
        }
    }
}

// grid: (n-blocks, m-blocks) — n is the FAST dimension so CTAs sharing an A-slice
// run concurrently and A is streamed from HBM once (critical for FFN2 where A > L2)
template<int ACT>
__global__ __launch_bounds__(256, 2)
void k_gemm_mma(const float* __restrict__ A, const float* __restrict__ W,
                const float* __restrict__ bias, float* __restrict__ C,
                int M, int N, int K)
{
    gemm_cp_body<ACT>(A, W, bias, C, M, N, K, blockIdx.y*128, blockIdx.x*128);
}

__global__ __launch_bounds__(256, 2)
void k_gemm_qkv(const float* __restrict__ A,
                const float* __restrict__ W0, const float* __restrict__ W1, const float* __restrict__ W2p,
                const float* __restrict__ b0, const float* __restrict__ b1, const float* __restrict__ b2p,
                float* __restrict__ o0, float* __restrict__ o1, float* __restrict__ o2)
{
    const float* W = (blockIdx.z==0) ? W0 : (blockIdx.z==1) ? W1 : W2p;
    const float* bs = (blockIdx.z==0) ? b0 : (blockIdx.z==1) ? b1 : b2p;
    float* C = (blockIdx.z==0) ? o0 : (blockIdx.z==1) ? o1 : o2;
    gemm_cp_body<2>(A, W, bs, C, BLROWS, DD, DD, blockIdx.y*128, blockIdx.x*128);
}

// ---------------- tensor-core flash attention: 128-row Q tile, 8 warps ----------------
// Q/K/V pre-rounded by producer GEMMs. Per-warp math identical to the 64-row version
// (each warp still owns 16 Q rows) -> bit-identical numerics, half the KV traffic.
#define ATT_SMEM ((128*68 + 64*68 + 64*72 + 128*68)*4)   // 105472 B

__global__ __launch_bounds__(256)
void k_attn_mma(const int* __restrict__ lens_p, float* __restrict__ O){
    extern __shared__ float sm[];
    float (*Qs)[68] = (float(*)[68])sm;                                  // 128x68
    float (*Ks)[68] = (float(*)[68])(sm + 128*68);                       // 64x68
    float (*Vs)[72] = (float(*)[72])(sm + 128*68 + 64*68);               // 64x72
    float (*Ps)[68] = (float(*)[68])(sm + 128*68 + 64*68 + 64*72);       // 128x68
    int bh = blockIdx.y;
    int b = bh >> 3, h = bh & 7;
    int q0 = blockIdx.x*128;
    int tid = threadIdx.x, lane = tid&31, w = tid>>5;
    int g = lane>>2, q = lane&3;
    int len = lens_p[b]; len = min(max(len,1),SS);
    int valid = len + TT;
    const float* Qg = g_q + (size_t)b*LL*DD + h*64;
    const float* Kg = g_k + (size_t)b*LL*DD + h*64;
    const float* Vg = g_v + (size_t)b*LL*DD + h*64;

    // load Q tile: 128 rows x 16 float4 chunks = 2048 / 256 threads = 8 iters
    #pragma unroll
    for (int i=0;i<8;i++){
        int s = tid + i*256;
        int r = s>>4, c4 = (s&15)*4;
        int gr = q0+r;
        float4 v = (gr<LL) ? *(const float4*)(Qg + (size_t)gr*DD + c4) : make_float4(0,0,0,0);
        *(float4*)&Qs[r][c4] = v;
    }
    __syncthreads();
    unsigned qf[8][4];
    {
        int mr = w*16 + g;
        #pragma unroll
        for (int kc=0;kc<8;kc++){
            qf[kc][0]=__float_as_uint(Qs[mr  ][kc*8+q  ]);
            qf[kc][1]=__float_as_uint(Qs[mr+8][kc*8+q  ]);
            qf[kc][2]=__float_as_uint(Qs[mr  ][kc*8+q+4]);
            qf[kc][3]=__float_as_uint(Qs[mr+8][kc*8+q+4]);
        }
    }
    float m0v=-1e30f, m1v=-1e30f, l0=0.f, l1=0.f;
    float oacc[8][4];
    #pragma unroll
    for (int nt=0;nt<8;nt++){ oacc[nt][0]=0.f;oacc[nt][1]=0.f;oacc[nt][2]=0.f;oacc[nt][3]=0.f; }

    const int nkt = (LL+63)/64;
    for (int kt=0; kt<nkt; kt++){
        int k0r = kt*64;
        // load K/V tile: 64 rows x 16 chunks = 1024 / 256 = 4 iters
        #pragma unroll
        for (int i=0;i<4;i++){
            int s = tid + i*256;
            int r = s>>4, c4 = (s&15)*4;
            int gr = k0r+r;
            float4 kv4 = (gr<LL) ? *(const float4*)(Kg + (size_t)gr*DD + c4) : make_float4(0,0,0,0);
            float4 vv4 = (gr<LL) ? *(const float4*)(Vg + (size_t)gr*DD + c4) : make_float4(0,0,0,0);
            *(float4*)&Ks[r][c4] = kv4;
            *(float4*)&Vs[r][c4] = vv4;
        }
        __syncthreads();

        float sacc[8][4];
        #pragma unroll
        for (int nt=0;nt<8;nt++){ sacc[nt][0]=0.f;sacc[nt][1]=0.f;sacc[nt][2]=0.f;sacc[nt][3]=0.f; }
        #pragma unroll
        for (int kc=0;kc<8;kc++){
            #pragma unroll
            for (int nt=0;nt<8;nt++){
                unsigned b0 = __float_as_uint(Ks[nt*8+g][kc*8+q  ]);
                unsigned b1 = __float_as_uint(Ks[nt*8+g][kc*8+q+4]);
                mma_tf32(sacc[nt], qf[kc], b0, b1);
            }
        }
        float ml0=-1e30f, ml1=-1e30f;
        #pragma unroll
        for (int nt=0;nt<8;nt++){
            int c = k0r + nt*8 + 2*q;
            float msk0 = (c   >= valid) ? -10000.f : 0.f;
            float msk1 = (c+1 >= valid) ? -10000.f : 0.f;
            sacc[nt][0] = sacc[nt][0]*0.125f + msk0;
            sacc[nt][1] = sacc[nt][1]*0.125f + msk1;
            sacc[nt][2] = sacc[nt][2]*0.125f + msk0;
            sacc[nt][3] = sacc[nt][3]*0.125f + msk1;
            ml0 = fmaxf(ml0, fmaxf(sacc[nt][0], sacc[nt][1]));
            ml1 = fmaxf(ml1, fmaxf(sacc[nt][2], sacc[nt][3]));
        }
        ml0 = fmaxf(ml0, __shfl_xor_sync(0xffffffffu, ml0, 1));
        ml0 = fmaxf(ml0, __shfl_xor_sync(0xffffffffu, ml0, 2));
        ml1 = fmaxf(ml1, __shfl_xor_sync(0xffffffffu, ml1, 1));
        ml1 = fmaxf(ml1, __shfl_xor_sync(0xffffffffu, ml1, 2));
        float mn0 = fmaxf(m0v, ml0), mn1 = fmaxf(m1v, ml1);
        float al0 = __expf(m0v - mn0), al1 = __expf(m1v - mn1);
        m0v = mn0; m1v = mn1;
        float ps0 = 0.f, ps1 = 0.f;
        int mr = w*16 + g;
        #pragma unroll
        for (int nt=0;nt<8;nt++){
            float p0 = __expf(sacc[nt][0]-mn0);
            float p1 = __expf(sacc[nt][1]-mn0);
            float p2 = __expf(sacc[nt][2]-mn1);
            float p3 = __expf(sacc[nt][3]-mn1);
            ps0 += p0+p1; ps1 += p2+p3;
            int pc = nt*8 + 2*q;
            Ps[mr  ][pc]   = rnd_tf32(p0);
            Ps[mr  ][pc+1] = rnd_tf32(p1);
            Ps[mr+8][pc]   = rnd_tf32(p2);
            Ps[mr+8][pc+1] = rnd_tf32(p3);
        }
        ps0 += __shfl_xor_sync(0xffffffffu, ps0, 1);
        ps0 += __shfl_xor_sync(0xffffffffu, ps0, 2);
        ps1 += __shfl_xor_sync(0xffffffffu, ps1, 1);
        ps1 += __shfl_xor_sync(0xffffffffu, ps1, 2);
        l0 = l0*al0 + ps0;
        l1 = l1*al1 + ps1;
        #pragma unroll
        for (int nt=0;nt<8;nt++){
            oacc[nt][0]*=al0; oacc[nt][1]*=al0;
            oacc[nt][2]*=al1; oacc[nt][3]*=al1;
        }
        __syncwarp();
        #pragma unroll
        for (int kc=0;kc<8;kc++){
            unsigned pf[4];
            pf[0]=__float_as_uint(Ps[mr  ][kc*8+q  ]);
            pf[1]=__float_as_uint(Ps[mr+8][kc*8+q  ]);
            pf[2]=__float_as_uint(Ps[mr  ][kc*8+q+4]);
            pf[3]=__float_as_uint(Ps[mr+8][kc*8+q+4]);
            #pragma unroll
            for (int nt=0;nt<8;nt++){
                unsigned b0 = __float_as_uint(Vs[kc*8+q  ][nt*8+g]);
                unsigned b1 = __float_as_uint(Vs[kc*8+q+4][nt*8+g]);
                mma_tf32(oacc[nt], pf, b0, b1);
            }
        }
        __syncthreads();
    }
    float inv0 = 1.f/l0, inv1 = 1.f/l1;
    int r0 = q0 + w*16 + g;
    float* Ob = O + (size_t)b*LL*DD + h*64;
    #pragma unroll
    for (int nt=0;nt<8;nt++){
        int c = nt*8 + 2*q;
        if (r0 < LL)   *(float2*)(Ob + (size_t)r0*DD + c)     = make_float2(rnd_tf32(oacc[nt][0]*inv0), rnd_tf32(oacc[nt][1]*inv0));
        if (r0+8 < LL) *(float2*)(Ob + (size_t)(r0+8)*DD + c) = make_float2(rnd_tf32(oacc[nt][2]*inv1), rnd_tf32(oacc[nt][3]*inv1));
    }
}

// ---------------- residual + LayerNorm (warp per row) + tf32 dual-write ----------------
__global__ __launch_bounds__(256)
void k_addln(float* __restrict__ hid, const float* __restrict__ t,
             const float* __restrict__ gg, const float* __restrict__ bbv){
    int w = threadIdx.x >> 5, lane = threadIdx.x & 31;
    int r = blockIdx.x*8 + w;
    float* hp = hid + (size_t)r*DD;
    const float* tp = t + (size_t)r*DD;
    float4 x[4];
    float s = 0.f;
    #pragma unroll
    for (int i=0;i<4;i++){
        float4 a = *(const float4*)(hp + (lane + i*32)*4);
        float4 c = *(const float4*)(tp + (lane + i*32)*4);
        x[i].x=a.x+c.x; x[i].y=a.y+c.y; x[i].z=a.z+c.z; x[i].w=a.w+c.w;
        s += x[i].x + x[i].y + x[i].z + x[i].w;
    }
    s = warp_red_sum(s);
    float mean = s*(1.f/512.f);
    float q = 0.f;
    #pragma unroll
    for (int i=0;i<4;i++){
        x[i].x-=mean; x[i].y-=mean; x[i].z-=mean; x[i].w-=mean;
        q += x[i].x*x[i].x + x[i].y*x[i].y + x[i].z*x[i].z + x[i].w*x[i].w;
    }
    q = warp_red_sum(q);
    float inv = rsqrtf(q*(1.f/512.f) + 1e-12f);
    float* cp = g_hconv + (size_t)r*DD;
    #pragma unroll
    for (int i=0;i<4;i++){
        float4 gv = *(const float4*)(gg + (lane + i*32)*4);
        float4 bv = *(const float4*)(bbv + (lane + i*32)*4);
        float4 o;
        o.x = x[i].x*inv*gv.x + bv.x;
        o.y = x[i].y*inv*gv.y + bv.y;
        o.z = x[i].z*inv*gv.z + bv.z;
        o.w = x[i].w*inv*gv.w + bv.w;
        *(float4*)(hp + (lane + i*32)*4) = o;
        uint4 tc; tc.x=f2tf32(o.x); tc.y=f2tf32(o.y); tc.z=f2tf32(o.z); tc.w=f2tf32(o.w);
        *(uint4*)(cp + (lane + i*32)*4) = tc;
    }
}

// ---------------- host ----------------
extern "C" void kernel_launch(void* const* d_in, const int* in_sizes, int n_in,
                              void* d_out, int out_size) {
    const int*   input_ids = (const int*)  d_in[0];
    const int*   seq_lens  = (const int*)  d_in[1];
    const float* embed     = (const float*)d_in[2];
    const float* W_dec     = (const float*)d_in[3];
    const float* b_dec     = (const float*)d_in[4];
    const float* mem_W1    = (const float*)d_in[5];
    const float* mem_b1    = (const float*)d_in[6];
    const float* mem_W2    = (const float*)d_in[7];
    const float* mem_b2    = (const float*)d_in[8];
    const float* mem_ln_g  = (const float*)d_in[9];
    const float* mem_ln_b  = (const float*)d_in[10];
    const float* Wq = (const float*)d_in[11];
    const float* bq = (const float*)d_in[12];
    const float* Wk = (const float*)d_in[13];
    const float* bk = (const float*)d_in[14];
    const float* Wv = (const float*)d_in[15];
    const float* bv = (const float*)d_in[16];
    const float* Wo = (const float*)d_in[17];
    const float* bo = (const float*)d_in[18];
    const float* ln1_g = (const float*)d_in[19];
    const float* ln1_b = (const float*)d_in[20];
    const float* Wi = (const float*)d_in[21];
    const float* bi = (const float*)d_in[22];
    const float* Wf = (const float*)d_in[23];
    const float* bf = (const float*)d_in[24];
    const float* ln2_g = (const float*)d_in[25];
    const float* ln2_b = (const float*)d_in[26];

    float* hidden = (float*)d_out;

    float *p_q, *p_k, *p_v, *p_ctx, *p_t, *p_ff, *p_hmem, *p_hconv, *p_wconv;
    cudaGetSymbolAddress((void**)&p_q,   g_q);
    cudaGetSymbolAddress((void**)&p_k,   g_k);
    cudaGetSymbolAddress((void**)&p_v,   g_v);
    cudaGetSymbolAddress((void**)&p_ctx, g_ctx);
    cudaGetSymbolAddress((void**)&p_t,   g_t);
    cudaGetSymbolAddress((void**)&p_ff,  g_ff);
    cudaGetSymbolAddress((void**)&p_hmem, g_hmem);
    cudaGetSymbolAddress((void**)&p_hconv, g_hconv);
    cudaGetSymbolAddress((void**)&p_wconv, g_wconv);

    cudaFuncSetAttribute(k_attn_mma, cudaFuncAttributeMaxDynamicSharedMemorySize, ATT_SMEM);
    cudaFuncSetAttribute(k_gemm_mma<0>, cudaFuncAttributeMaxDynamicSharedMemorySize, GEMM_SMEM);
    cudaFuncSetAttribute(k_gemm_mma<1>, cudaFuncAttributeMaxDynamicSharedMemorySize, GEMM_SMEM);
    cudaFuncSetAttribute(k_gemm_qkv,    cudaFuncAttributeMaxDynamicSharedMemorySize, GEMM_SMEM);

    // one-time weight tf32 conversion (float4)
    k_conv<<<(1048576/4+255)/256, 256>>>(Wq,     p_wconv + WQ_OFF, 1048576/4);
    k_conv<<<(1048576/4+255)/256, 256>>>(Wk,     p_wconv + WK_OFF, 1048576/4);
    k_conv<<<(1048576/4+255)/256, 256>>>(Wv,     p_wconv + WV_OFF, 1048576/4);
    k_conv<<<(1048576/4+255)/256, 256>>>(Wo,     p_wconv + WO_OFF, 1048576/4);
    k_conv<<<(4194304/4+255)/256, 256>>>(Wi,     p_wconv + WI_OFF, 4194304/4);
    k_conv<<<(4194304/4+255)/256, 256>>>(Wf,     p_wconv + WF_OFF, 4194304/4);
    k_conv<<<(524288/4+255)/256, 256>>>(mem_W2, p_wconv + W2_OFF, 524288/4);

    // topic memory
    k_wdec_softmax<<<TT, 1024>>>(W_dec, b_dec);
    k_mem_gemm1<<<dim3(8, KSPLIT), 256>>>(mem_W1);
    k_mem_reduce<<<(TT*1024+255)/256, 256>>>(mem_b1);
    k_gemm_mma<0><<<dim3(4, 1), 256, GEMM_SMEM>>>(p_hmem, p_wconv + W2_OFF, mem_b2, p_t, TT, DD, 1024);
    k_ln_topic<<<TT, 512>>>(p_t, mem_ln_g, mem_ln_b);

    // build hidden into d_out (+ tf32 copy)
    k_build_hidden<<<BLROWS, 128>>>(input_ids, seq_lens, embed, hidden);

    const int MB = (BLROWS + 127)/128;  // 141
    for (int l = 0; l < NLAYER; l++) {
        const float* wq = p_wconv + WQ_OFF + (size_t)l*DD*DD;
        const float* wk = p_wconv + WK_OFF + (size_t)l*DD*DD;
        const float* wv = p_wconv + WV_OFF + (size_t)l*DD*DD;
        const float* wo = p_wconv + WO_OFF + (size_t)l*DD*DD;
        const float* wi = p_wconv + WI_OFF + (size_t)l*DD*FFDIM;
        const float* wf = p_wconv + WF_OFF + (size_t)l*FFDIM*DD;

        k_gemm_qkv<<<dim3(DD/128, MB, 3), 256, GEMM_SMEM>>>(p_hconv, wq, wk, wv,
                                                 bq + l*DD, bk + l*DD, bv + l*DD,
                                                 p_q, p_k, p_v);

        k_attn_mma<<<dim3((LL+127)/128, BB*HH), 256, ATT_SMEM>>>(seq_lens, p_ctx);

        k_gemm_mma<0><<<dim3(DD/128, MB), 256, GEMM_SMEM>>>(p_ctx, wo, bo + l*DD, p_t, BLROWS, DD, DD);
        k_addln<<<BLROWS/8, 256>>>(hidden, p_t, ln1_g + l*DD, ln1_b + l*DD);

        k_gemm_mma<1><<<dim3(FFDIM/128, MB), 256, GEMM_SMEM>>>(p_hconv, wi, bi + l*FFDIM, p_ff, BLROWS, FFDIM, DD);
        k_gemm_mma<0><<<dim3(DD/128, MB), 256, GEMM_SMEM>>>(p_ff, wf, bf + l*DD, p_t, BLROWS, DD, FFDIM);
        k_addln<<<BLROWS/8, 256>>>(hidden, p_t, ln2_g + l*DD, ln2_b + l*DD);
    }
}

// round 11
// speedup vs baseline: 1.0899x; 1.0899x over previous
#include <cuda_runtime.h>
#include <cuda_bf16.h>
#include <math.h>

#define BB 32
#define SS 512
#define TT 50
#define LL 562      // S+T
#define DD 512
#define HH 8
#define FFDIM 2048
#define NLAYER 4
#define VBB 30000
#define BLROWS (BB*LL)   // 17984
#define KSPLIT 75
#define KCHUNK 400

// weight-conversion buffer offsets (floats)
#define WQ_OFF 0
#define WK_OFF 1048576
#define WV_OFF 2097152
#define WO_OFF 3145728
#define WI_OFF 4194304
#define WF_OFF 8388608
#define W2_OFF 12582912
#define WCONV_TOTAL 13107200

// ---------------- scratch ----------------
__device__ float g_wd[TT*VBB];
__device__ float g_part[KSPLIT*TT*1024];
__device__ float g_hmem[TT*1024];
__device__ float g_topic[TT*DD];
__device__ float g_q[BLROWS*DD];
__device__ float g_k[BLROWS*DD];
__device__ float g_v[BLROWS*DD];
__device__ float g_ctx[BLROWS*DD];
__device__ float g_t[BLROWS*DD];
__device__ float g_ff[(size_t)BLROWS*FFDIM];
__device__ float g_hconv[BLROWS*DD];
__device__ float g_wconv[WCONV_TOTAL];

// ---------------- helpers ----------------
__device__ __forceinline__ float warp_red_sum(float v){
    #pragma unroll
    for (int o=16;o>0;o>>=1) v += __shfl_xor_sync(0xffffffffu, v, o);
    return v;
}
__device__ __forceinline__ float warp_red_max(float v){
    #pragma unroll
    for (int o=16;o>0;o>>=1) v = fmaxf(v, __shfl_xor_sync(0xffffffffu, v, o));
    return v;
}
__device__ __forceinline__ unsigned f2tf32(float x){
    unsigned r;
    asm("cvt.rna.tf32.f32 %0, %1;" : "=r"(r) : "f"(x));
    return r;
}
__device__ __forceinline__ float rnd_tf32(float x){ return __uint_as_float(f2tf32(x)); }
__device__ __forceinline__ void mma_tf32(float* d, const unsigned* a, unsigned b0, unsigned b1){
    asm volatile(
        "mma.sync.aligned.m16n8k8.row.col.f32.tf32.tf32.f32 "
        "{%0,%1,%2,%3}, {%4,%5,%6,%7}, {%8,%9}, {%0,%1,%2,%3};"
        : "+f"(d[0]), "+f"(d[1]), "+f"(d[2]), "+f"(d[3])
        : "r"(a[0]), "r"(a[1]), "r"(a[2]), "r"(a[3]), "r"(b0), "r"(b1));
}

// tf32-round a tensor (float4 vectorized)
__global__ void k_conv(const float* __restrict__ src, float* __restrict__ dst, int n4){
    int i = blockIdx.x*256 + threadIdx.x;
    if (i >= n4) return;
    float4 v = ((const float4*)src)[i];
    uint4 t; t.x=f2tf32(v.x); t.y=f2tf32(v.y); t.z=f2tf32(v.z); t.w=f2tf32(v.w);
    ((uint4*)dst)[i] = t;
}

// ---------------- topic memory pipeline ----------------
__global__ void k_wdec_softmax(const float* __restrict__ W, const float* __restrict__ bvec){
    int row = blockIdx.x, tid = threadIdx.x;
    __shared__ float red[32];
    const float* w = W + (size_t)row*VBB;
    float m = -1e30f;
    for (int i=tid;i<VBB;i+=1024) m = fmaxf(m, w[i]+bvec[i]);
    m = warp_red_max(m);
    if ((tid&31)==0) red[tid>>5]=m;
    __syncthreads();
    float mm = red[0];
    #pragma unroll
    for (int i=1;i<32;i++) mm = fmaxf(mm, red[i]);
    float s = 0.f;
    for (int i=tid;i<VBB;i+=1024) s += __expf(w[i]+bvec[i]-mm);
    s = warp_red_sum(s);
    __syncthreads();
    if ((tid&31)==0) red[tid>>5]=s;
    __syncthreads();
    float ss = 0.f;
    #pragma unroll
    for (int i=0;i<32;i++) ss += red[i];
    float inv = 1.0f/ss;
    for (int i=tid;i<VBB;i+=1024) g_wd[(size_t)row*VBB+i] = __expf(w[i]+bvec[i]-mm)*inv;
}

__global__ void k_mem_gemm1(const float* __restrict__ W1){
    __shared__ float wds[16][52];
    __shared__ float Ws[16][128];
    int n0 = blockIdx.x*128;
    int k0 = blockIdx.y*KCHUNK;
    int tid = threadIdx.x;
    int n = tid & 127, mb = (tid>>7)*25;
    float acc[25];
    #pragma unroll
    for (int i=0;i<25;i++) acc[i]=0.f;
    for (int kt=0; kt<KCHUNK; kt+=16){
        int kb = k0+kt;
        for (int x=tid;x<800;x+=256){ int m=x>>4, kk=x&15; wds[kk][m]=g_wd[(size_t)m*VBB + kb + kk]; }
        #pragma unroll
        for (int jj=0;jj<2;jj++){
            int idx = tid + jj*256;
            int r = idx>>5, c4 = (idx&31)*4;
            *(float4*)&Ws[r][c4] = *(const float4*)(W1 + (size_t)(kb+r)*1024 + n0 + c4);
        }
        __syncthreads();
        #pragma unroll
        for (int kk=0;kk<16;kk++){
            float w = Ws[kk][n];
            #pragma unroll
            for (int i=0;i<25;i++) acc[i] += wds[kk][mb+i]*w;
        }
        __syncthreads();
    }
    float* out = g_part + (size_t)blockIdx.y*(TT*1024);
    #pragma unroll
    for (int i=0;i<25;i++) out[(mb+i)*1024 + n0 + n] = acc[i];
}

__global__ void k_mem_reduce(const float* __restrict__ b1){
    int i = blockIdx.x*256 + threadIdx.x;
    if (i >= TT*1024) return;
    float s = 0.f;
    for (int ks=0; ks<KSPLIT; ks++) s += g_part[(size_t)ks*(TT*1024) + i];
    s += b1[i & 1023];
    g_hmem[i] = rnd_tf32(fmaxf(s, 0.f));
}

// LN over g_t[50,512] -> g_topic
__global__ __launch_bounds__(512)
void k_ln_topic(const float* __restrict__ src,
                const float* __restrict__ gg, const float* __restrict__ bbv){
    __shared__ float red[16];
    int row = blockIdx.x, tid = threadIdx.x;
    float a = src[row*512+tid];
    float s = warp_red_sum(a);
    if ((tid&31)==0) red[tid>>5]=s;
    __syncthreads();
    float tot=0.f;
    #pragma unroll
    for (int i=0;i<16;i++) tot+=red[i];
    float mean = tot*(1.f/512.f);
    float d = a-mean;
    float q = warp_red_sum(d*d);
    __syncthreads();
    if ((tid&31)==0) red[tid>>5]=q;
    __syncthreads();
    float vq=0.f;
    #pragma unroll
    for (int i=0;i<16;i++) vq+=red[i];
    float inv = rsqrtf(vq*(1.f/512.f) + 1e-12f);
    g_topic[row*512+tid] = d*inv*gg[tid] + bbv[tid];
}

// build hidden into d_out + tf32 copy into g_hconv
__global__ void k_build_hidden(const int* __restrict__ ids, const int* __restrict__ lens_p,
                               const float* __restrict__ embed, float* __restrict__ hid){
    int r = blockIdx.x;
    int b = r / LL, j = r % LL;
    int len = lens_p[b]; len = min(max(len,1),SS);
    const float* src;
    if (j >= len && j < len+TT){
        src = g_topic + (size_t)(j-len)*DD;
    } else {
        int sj = (j < len) ? j : (j - TT);
        sj = min(max(sj,0), SS-1);
        src = embed + (size_t)ids[b*SS + sj]*DD;
    }
    float4 v = ((const float4*)src)[threadIdx.x];
    ((float4*)(hid + (size_t)r*DD))[threadIdx.x] = v;
    uint4 t; t.x=f2tf32(v.x); t.y=f2tf32(v.y); t.z=f2tf32(v.z); t.w=f2tf32(v.w);
    ((uint4*)(g_hconv + (size_t)r*DD))[threadIdx.x] = t;
}

// ---------------- TF32 GEMM: cp.async 2-stage, 2 CTAs/SM ----------------
// operands must already be tf32-rounded.
// ACT: 0 = plain, 1 = gelu + tf32-round output, 2 = tf32-round output
#define AS_F (128*36)            // 4608 floats
#define WS_F (32*136)            // 4352 floats
#define STG_F (AS_F + WS_F)      // 8960 floats = 35840 B / stage
#define GEMM_SMEM (2*STG_F*4)    // 71680 B

template<int ACT>
__device__ __forceinline__
void gemm_cp_body(const float* __restrict__ A, const float* __restrict__ W,
                  const float* __restrict__ bias, float* __restrict__ C,
                  int M, int N, int K, int m0, int n0)
{
    extern __shared__ float sm_[];
    const int tid = threadIdx.x;
    const int lane = tid & 31, warp = tid >> 5;
    const int wm = warp >> 2, wn = warp & 3;
    const int q = lane & 3, g = lane >> 2;

    float acc[4][4][4];
    #pragma unroll
    for (int a=0;a<4;a++)
        #pragma unroll
        for (int b=0;b<4;b++)
            #pragma unroll
            for (int c=0;c<4;c++) acc[a][b][c]=0.f;

    const int am = tid>>3, akv = tid&7;           // A: row am, 16B chunk akv
    const int wk = tid>>5, wnv = tid&31;          // W: row wk, 16B chunk wnv

    { // issue stage 0
        float* As = sm_;
        float* Ws = sm_ + AS_F;
        #pragma unroll
        for (int i=0;i<4;i++){
            int m = am + i*32;
            unsigned dst = (unsigned)__cvta_generic_to_shared(&As[m*36 + akv*4]);
            const float* src = A + (size_t)(m0+m)*K + akv*4;
            int sz = (m0+m < M) ? 16 : 0;
            asm volatile("cp.async.ca.shared.global [%0],[%1],16,%2;\n" :: "r"(dst), "l"(src), "r"(sz));
        }
        #pragma unroll
        for (int i=0;i<4;i++){
            int kk = wk + i*8;
            unsigned dst = (unsigned)__cvta_generic_to_shared(&Ws[kk*136 + wnv*4]);
            const float* src = W + (size_t)kk*N + n0 + wnv*4;
            asm volatile("cp.async.ca.shared.global [%0],[%1],16;\n" :: "r"(dst), "l"(src));
        }
        asm volatile("cp.async.commit_group;\n");
    }

    const int nk = K >> 5;
    for (int kt = 0; kt < nk; kt++){
        asm volatile("cp.async.wait_group 0;\n");
        __syncthreads();
        if (kt+1 < nk){
            int k0 = (kt+1)*32;
            float* As = sm_ + ((kt+1)&1)*STG_F;
            float* Ws = As + AS_F;
            #pragma unroll
            for (int i=0;i<4;i++){
                int m = am + i*32;
                unsigned dst = (unsigned)__cvta_generic_to_shared(&As[m*36 + akv*4]);
                const float* src = A + (size_t)(m0+m)*K + k0 + akv*4;
                int sz = (m0+m < M) ? 16 : 0;
                asm volatile("cp.async.ca.shared.global [%0],[%1],16,%2;\n" :: "r"(dst), "l"(src), "r"(sz));
            }
            #pragma unroll
            for (int i=0;i<4;i++){
                int kk = wk + i*8;
                unsigned dst = (unsigned)__cvta_generic_to_shared(&Ws[kk*136 + wnv*4]);
                const float* src = W + (size_t)(k0+kk)*N + n0 + wnv*4;
                asm volatile("cp.async.ca.shared.global [%0],[%1],16;\n" :: "r"(dst), "l"(src));
            }
            asm volatile("cp.async.commit_group;\n");
        }
        const float* As = sm_ + (kt&1)*STG_F;
        const float* Ws = As + AS_F;
        #pragma unroll
        for (int k8=0;k8<4;k8++){
            unsigned af[4][4], bf[4][2];
            #pragma unroll
            for (int mi=0;mi<4;mi++){
                int mr = wm*64 + mi*16 + g;
                af[mi][0] = __float_as_uint(As[mr*36     + k8*8+q  ]);
                af[mi][1] = __float_as_uint(As[(mr+8)*36 + k8*8+q  ]);
                af[mi][2] = __float_as_uint(As[mr*36     + k8*8+q+4]);
                af[mi][3] = __float_as_uint(As[(mr+8)*36 + k8*8+q+4]);
            }
            #pragma unroll
            for (int nj=0;nj<4;nj++){
                int nc = wn*32 + nj*8 + g;
                bf[nj][0] = __float_as_uint(Ws[(k8*8+q  )*136 + nc]);
                bf[nj][1] = __float_as_uint(Ws[(k8*8+q+4)*136 + nc]);
            }
            #pragma unroll
            for (int mi=0;mi<4;mi++)
                #pragma unroll
                for (int nj=0;nj<4;nj++)
                    mma_tf32(acc[mi][nj], af[mi], bf[nj][0], bf[nj][1]);
        }
    }

    #pragma unroll
    for (int nj=0;nj<4;nj++){
        int c0 = n0 + wn*32 + nj*8 + q*2;
        float bv0 = bias[c0], bv1 = bias[c0+1];
        #pragma unroll
        for (int mi=0;mi<4;mi++){
            int r0 = m0 + wm*64 + mi*16 + g;
            float v0 = acc[mi][nj][0] + bv0;
            float v1 = acc[mi][nj][1] + bv1;
            float v2 = acc[mi][nj][2] + bv0;
            float v3 = acc[mi][nj][3] + bv1;
            if (ACT==1){
                v0 = rnd_tf32(0.5f*v0*(1.0f+erff(v0*0.70710678118654752f)));
                v1 = rnd_tf32(0.5f*v1*(1.0f+erff(v1*0.70710678118654752f)));
                v2 = rnd_tf32(0.5f*v2*(1.0f+erff(v2*0.70710678118654752f)));
                v3 = rnd_tf32(0.5f*v3*(1.0f+erff(v3*0.70710678118654752f)));
            }
            if (ACT==2){
                v0 = rnd_tf32(v0); v1 = rnd_tf32(v1);
                v2 = rnd_tf32(v2); v3 = rnd_tf32(v3);
            }
            if (r0 < M)   { *(float2*)(C + (size_t)r0*N + c0) = make_float2(v0,v1); }
            if (r0+8 < M) { *(float2*)(C + (size_t)(r0+8)*N + c0) = make_float2(v2,v3); }
        }
    }
}

template<int ACT>
__global__ __launch_bounds__(256, 2)
void k_gemm_mma(const float* __restrict__ A, const float* __restrict__ W,
                const float* __restrict__ bias, float* __restrict__ C,
                int M, int N, int K)
{
    gemm_cp_body<ACT>(A, W, bias, C, M, N, K, blockIdx.y*128, blockIdx.x*128);
}

__global__ __launch_bounds__(256, 2)
void k_gemm_qkv(const float* __restrict__ A,
                const float* __restrict__ W0, const float* __restrict__ W1, const float* __restrict__ W2p,
                const float* __restrict__ b0, const float* __restrict__ b1, const float* __restrict__ b2p,
                float* __restrict__ o0, float* __restrict__ o1, float* __restrict__ o2)
{
    const float* W = (blockIdx.z==0) ? W0 : (blockIdx.z==1) ? W1 : W2p;
    const float* bs = (blockIdx.z==0) ? b0 : (blockIdx.z==1) ? b1 : b2p;
    float* C = (blockIdx.z==0) ? o0 : (blockIdx.z==1) ? o1 : o2;
    gemm_cp_body<2>(A, W, bs, C, BLROWS, DD, DD, blockIdx.y*128, blockIdx.x*128);
}

// ---------------- tensor-core flash attention: 128-row Q tile, 8 warps ----------------
// Q/K/V pre-rounded by producer GEMMs.
// KV loop clamped to ceil(valid/64): fully-masked tiles contribute exactly 0
// (exp underflows to 0.0f; row max unchanged since tile 0 always has >=51 live keys).
#define ATT_SMEM ((128*68 + 64*68 + 64*72 + 128*68)*4)   // 105472 B

__global__ __launch_bounds__(256)
void k_attn_mma(const int* __restrict__ lens_p, float* __restrict__ O){
    extern __shared__ float sm[];
    float (*Qs)[68] = (float(*)[68])sm;                                  // 128x68
    float (*Ks)[68] = (float(*)[68])(sm + 128*68);                       // 64x68
    float (*Vs)[72] = (float(*)[72])(sm + 128*68 + 64*68);               // 64x72
    float (*Ps)[68] = (float(*)[68])(sm + 128*68 + 64*68 + 64*72);       // 128x68
    int bh = blockIdx.y;
    int b = bh >> 3, h = bh & 7;
    int q0 = blockIdx.x*128;
    int tid = threadIdx.x, lane = tid&31, w = tid>>5;
    int g = lane>>2, q = lane&3;
    int len = lens_p[b]; len = min(max(len,1),SS);
    int valid = len + TT;
    const float* Qg = g_q + (size_t)b*LL*DD + h*64;
    const float* Kg = g_k + (size_t)b*LL*DD + h*64;
    const float* Vg = g_v + (size_t)b*LL*DD + h*64;

    #pragma unroll
    for (int i=0;i<8;i++){
        int s = tid + i*256;
        int r = s>>4, c4 = (s&15)*4;
        int gr = q0+r;
        float4 v = (gr<LL) ? *(const float4*)(Qg + (size_t)gr*DD + c4) : make_float4(0,0,0,0);
        *(float4*)&Qs[r][c4] = v;
    }
    __syncthreads();
    unsigned qf[8][4];
    {
        int mr = w*16 + g;
        #pragma unroll
        for (int kc=0;kc<8;kc++){
            qf[kc][0]=__float_as_uint(Qs[mr  ][kc*8+q  ]);
            qf[kc][1]=__float_as_uint(Qs[mr+8][kc*8+q  ]);
            qf[kc][2]=__float_as_uint(Qs[mr  ][kc*8+q+4]);
            qf[kc][3]=__float_as_uint(Qs[mr+8][kc*8+q+4]);
        }
    }
    float m0v=-1e30f, m1v=-1e30f, l0=0.f, l1=0.f;
    float oacc[8][4];
    #pragma unroll
    for (int nt=0;nt<8;nt++){ oacc[nt][0]=0.f;oacc[nt][1]=0.f;oacc[nt][2]=0.f;oacc[nt][3]=0.f; }

    // clamp KV loop to tiles containing live keys (exact: masked tiles add 0)
    const int nkt = (valid + 63) >> 6;
    for (int kt=0; kt<nkt; kt++){
        int k0r = kt*64;
        #pragma unroll
        for (int i=0;i<4;i++){
            int s = tid + i*256;
            int r = s>>4, c4 = (s&15)*4;
            int gr = k0r+r;
            float4 kv4 = (gr<LL) ? *(const float4*)(Kg + (size_t)gr*DD + c4) : make_float4(0,0,0,0);
            float4 vv4 = (gr<LL) ? *(const float4*)(Vg + (size_t)gr*DD + c4) : make_float4(0,0,0,0);
            *(float4*)&Ks[r][c4] = kv4;
            *(float4*)&Vs[r][c4] = vv4;
        }
        __syncthreads();

        float sacc[8][4];
        #pragma unroll
        for (int nt=0;nt<8;nt++){ sacc[nt][0]=0.f;sacc[nt][1]=0.f;sacc[nt][2]=0.f;sacc[nt][3]=0.f; }
        #pragma unroll
        for (int kc=0;kc<8;kc++){
            #pragma unroll
            for (int nt=0;nt<8;nt++){
                unsigned b0 = __float_as_uint(Ks[nt*8+g][kc*8+q  ]);
                unsigned b1 = __float_as_uint(Ks[nt*8+g][kc*8+q+4]);
                mma_tf32(sacc[nt], qf[kc], b0, b1);
            }
        }
        float ml0=-1e30f, ml1=-1e30f;
        #pragma unroll
        for (int nt=0;nt<8;nt++){
            int c = k0r + nt*8 + 2*q;
            float msk0 = (c   >= valid) ? -10000.f : 0.f;
            float msk1 = (c+1 >= valid) ? -10000.f : 0.f;
            sacc[nt][0] = sacc[nt][0]*0.125f + msk0;
            sacc[nt][1] = sacc[nt][1]*0.125f + msk1;
            sacc[nt][2] = sacc[nt][2]*0.125f + msk0;
            sacc[nt][3] = sacc[nt][3]*0.125f + msk1;
            ml0 = fmaxf(ml0, fmaxf(sacc[nt][0], sacc[nt][1]));
            ml1 = fmaxf(ml1, fmaxf(sacc[nt][2], sacc[nt][3]));
        }
        ml0 = fmaxf(ml0, __shfl_xor_sync(0xffffffffu, ml0, 1));
        ml0 = fmaxf(ml0, __shfl_xor_sync(0xffffffffu, ml0, 2));
        ml1 = fmaxf(ml1, __shfl_xor_sync(0xffffffffu, ml1, 1));
        ml1 = fmaxf(ml1, __shfl_xor_sync(0xffffffffu, ml1, 2));
        float mn0 = fmaxf(m0v, ml0), mn1 = fmaxf(m1v, ml1);
        float al0 = __expf(m0v - mn0), al1 = __expf(m1v - mn1);
        m0v = mn0; m1v = mn1;
        float ps0 = 0.f, ps1 = 0.f;
        int mr = w*16 + g;
        #pragma unroll
        for (int nt=0;nt<8;nt++){
            float p0 = __expf(sacc[nt][0]-mn0);
            float p1 = __expf(sacc[nt][1]-mn0);
            float p2 = __expf(sacc[nt][2]-mn1);
            float p3 = __expf(sacc[nt][3]-mn1);
            ps0 += p0+p1; ps1 += p2+p3;
            int pc = nt*8 + 2*q;
            Ps[mr  ][pc]   = rnd_tf32(p0);
            Ps[mr  ][pc+1] = rnd_tf32(p1);
            Ps[mr+8][pc]   = rnd_tf32(p2);
            Ps[mr+8][pc+1] = rnd_tf32(p3);
        }
        ps0 += __shfl_xor_sync(0xffffffffu, ps0, 1);
        ps0 += __shfl_xor_sync(0xffffffffu, ps0, 2);
        ps1 += __shfl_xor_sync(0xffffffffu, ps1, 1);
        ps1 += __shfl_xor_sync(0xffffffffu, ps1, 2);
        l0 = l0*al0 + ps0;
        l1 = l1*al1 + ps1;
        #pragma unroll
        for (int nt=0;nt<8;nt++){
            oacc[nt][0]*=al0; oacc[nt][1]*=al0;
            oacc[nt][2]*=al1; oacc[nt][3]*=al1;
        }
        __syncwarp();
        #pragma unroll
        for (int kc=0;kc<8;kc++){
            unsigned pf[4];
            pf[0]=__float_as_uint(Ps[mr  ][kc*8+q  ]);
            pf[1]=__float_as_uint(Ps[mr+8][kc*8+q  ]);
            pf[2]=__float_as_uint(Ps[mr  ][kc*8+q+4]);
            pf[3]=__float_as_uint(Ps[mr+8][kc*8+q+4]);
            #pragma unroll
            for (int nt=0;nt<8;nt++){
                unsigned b0 = __float_as_uint(Vs[kc*8+q  ][nt*8+g]);
                unsigned b1 = __float_as_uint(Vs[kc*8+q+4][nt*8+g]);
                mma_tf32(oacc[nt], pf, b0, b1);
            }
        }
        __syncthreads();
    }
    float inv0 = 1.f/l0, inv1 = 1.f/l1;
    int r0 = q0 + w*16 + g;
    float* Ob = O + (size_t)b*LL*DD + h*64;
    #pragma unroll
    for (int nt=0;nt<8;nt++){
        int c = nt*8 + 2*q;
        if (r0 < LL)   *(float2*)(Ob + (size_t)r0*DD + c)     = make_float2(rnd_tf32(oacc[nt][0]*inv0), rnd_tf32(oacc[nt][1]*inv0));
        if (r0+8 < LL) *(float2*)(Ob + (size_t)(r0+8)*DD + c) = make_float2(rnd_tf32(oacc[nt][2]*inv1), rnd_tf32(oacc[nt][3]*inv1));
    }
}

// ---------------- residual + LayerNorm (warp per row) + tf32 dual-write ----------------
__global__ __launch_bounds__(256)
void k_addln(float* __restrict__ hid, const float* __restrict__ t,
             const float* __restrict__ gg, const float* __restrict__ bbv){
    int w = threadIdx.x >> 5, lane = threadIdx.x & 31;
    int r = blockIdx.x*8 + w;
    float* hp = hid + (size_t)r*DD;
    const float* tp = t + (size_t)r*DD;
    float4 x[4];
    float s = 0.f;
    #pragma unroll
    for (int i=0;i<4;i++){
        float4 a = *(const float4*)(hp + (lane + i*32)*4);
        float4 c = *(const float4*)(tp + (lane + i*32)*4);
        x[i].x=a.x+c.x; x[i].y=a.y+c.y; x[i].z=a.z+c.z; x[i].w=a.w+c.w;
        s += x[i].x + x[i].y + x[i].z + x[i].w;
    }
    s = warp_red_sum(s);
    float mean = s*(1.f/512.f);
    float q = 0.f;
    #pragma unroll
    for (int i=0;i<4;i++){
        x[i].x-=mean; x[i].y-=mean; x[i].z-=mean; x[i].w-=mean;
        q += x[i].x*x[i].x + x[i].y*x[i].y + x[i].z*x[i].z + x[i].w*x[i].w;
    }
    q = warp_red_sum(q);
    float inv = rsqrtf(q*(1.f/512.f) + 1e-12f);
    float* cp = g_hconv + (size_t)r*DD;
    #pragma unroll
    for (int i=0;i<4;i++){
        float4 gv = *(const float4*)(gg + (lane + i*32)*4);
        float4 bv = *(const float4*)(bbv + (lane + i*32)*4);
        float4 o;
        o.x = x[i].x*inv*gv.x + bv.x;
        o.y = x[i].y*inv*gv.y + bv.y;
        o.z = x[i].z*inv*gv.z + bv.z;
        o.w = x[i].w*inv*gv.w + bv.w;
        *(float4*)(hp + (lane + i*32)*4) = o;
        uint4 tc; tc.x=f2tf32(o.x); tc.y=f2tf32(o.y); tc.z=f2tf32(o.z); tc.w=f2tf32(o.w);
        *(uint4*)(cp + (lane + i*32)*4) = tc;
    }
}

// ---------------- host ----------------
extern "C" void kernel_launch(void* const* d_in, const int* in_sizes, int n_in,
                              void* d_out, int out_size) {
    const int*   input_ids = (const int*)  d_in[0];
    const int*   seq_lens  = (const int*)  d_in[1];
    const float* embed     = (const float*)d_in[2];
    const float* W_dec     = (const float*)d_in[3];
    const float* b_dec     = (const float*)d_in[4];
    const float* mem_W1    = (const float*)d_in[5];
    const float* mem_b1    = (const float*)d_in[6];
    const float* mem_W2    = (const float*)d_in[7];
    const float* mem_b2    = (const float*)d_in[8];
    const float* mem_ln_g  = (const float*)d_in[9];
    const float* mem_ln_b  = (const float*)d_in[10];
    const float* Wq = (const float*)d_in[11];
    const float* bq = (const float*)d_in[12];
    const float* Wk = (const float*)d_in[13];
    const float* bk = (const float*)d_in[14];
    const float* Wv = (const float*)d_in[15];
    const float* bv = (const float*)d_in[16];
    const float* Wo = (const float*)d_in[17];
    const float* bo = (const float*)d_in[18];
    const float* ln1_g = (const float*)d_in[19];
    const float* ln1_b = (const float*)d_in[20];
    const float* Wi = (const float*)d_in[21];
    const float* bi = (const float*)d_in[22];
    const float* Wf = (const float*)d_in[23];
    const float* bf = (const float*)d_in[24];
    const float* ln2_g = (const float*)d_in[25];
    const float* ln2_b = (const float*)d_in[26];

    float* hidden = (float*)d_out;

    float *p_q, *p_k, *p_v, *p_ctx, *p_t, *p_ff, *p_hmem, *p_hconv, *p_wconv;
    cudaGetSymbolAddress((void**)&p_q,   g_q);
    cudaGetSymbolAddress((void**)&p_k,   g_k);
    cudaGetSymbolAddress((void**)&p_v,   g_v);
    cudaGetSymbolAddress((void**)&p_ctx, g_ctx);
    cudaGetSymbolAddress((void**)&p_t,   g_t);
    cudaGetSymbolAddress((void**)&p_ff,  g_ff);
    cudaGetSymbolAddress((void**)&p_hmem, g_hmem);
    cudaGetSymbolAddress((void**)&p_hconv, g_hconv);
    cudaGetSymbolAddress((void**)&p_wconv, g_wconv);

    cudaFuncSetAttribute(k_attn_mma, cudaFuncAttributeMaxDynamicSharedMemorySize, ATT_SMEM);
    cudaFuncSetAttribute(k_gemm_mma<0>, cudaFuncAttributeMaxDynamicSharedMemorySize, GEMM_SMEM);
    cudaFuncSetAttribute(k_gemm_mma<1>, cudaFuncAttributeMaxDynamicSharedMemorySize, GEMM_SMEM);
    cudaFuncSetAttribute(k_gemm_qkv,    cudaFuncAttributeMaxDynamicSharedMemorySize, GEMM_SMEM);

    // one-time weight tf32 conversion (float4)
    k_conv<<<(1048576/4+255)/256, 256>>>(Wq,     p_wconv + WQ_OFF, 1048576/4);
    k_conv<<<(1048576/4+255)/256, 256>>>(Wk,     p_wconv + WK_OFF, 1048576/4);
    k_conv<<<(1048576/4+255)/256, 256>>>(Wv,     p_wconv + WV_OFF, 1048576/4);
    k_conv<<<(1048576/4+255)/256, 256>>>(Wo,     p_wconv + WO_OFF, 1048576/4);
    k_conv<<<(4194304/4+255)/256, 256>>>(Wi,     p_wconv + WI_OFF, 4194304/4);
    k_conv<<<(4194304/4+255)/256, 256>>>(Wf,     p_wconv + WF_OFF, 4194304/4);
    k_conv<<<(524288/4+255)/256, 256>>>(mem_W2, p_wconv + W2_OFF, 524288/4);

    // topic memory
    k_wdec_softmax<<<TT, 1024>>>(W_dec, b_dec);
    k_mem_gemm1<<<dim3(8, KSPLIT), 256>>>(mem_W1);
    k_mem_reduce<<<(TT*1024+255)/256, 256>>>(mem_b1);
    k_gemm_mma<0><<<dim3(4, 1), 256, GEMM_SMEM>>>(p_hmem, p_wconv + W2_OFF, mem_b2, p_t, TT, DD, 1024);
    k_ln_topic<<<TT, 512>>>(p_t, mem_ln_g, mem_ln_b);

    // build hidden into d_out (+ tf32 copy)
    k_build_hidden<<<BLROWS, 128>>>(input_ids, seq_lens, embed, hidden);

    const int MB = (BLROWS + 127)/128;  // 141
    for (int l = 0; l < NLAYER; l++) {
        const float* wq = p_wconv + WQ_OFF + (size_t)l*DD*DD;
        const float* wk = p_wconv + WK_OFF + (size_t)l*DD*DD;
        const float* wv = p_wconv + WV_OFF + (size_t)l*DD*DD;
        const float* wo = p_wconv + WO_OFF + (size_t)l*DD*DD;
        const float* wi = p_wconv + WI_OFF + (size_t)l*DD*FFDIM;
        const float* wf = p_wconv + WF_OFF + (size_t)l*FFDIM*DD;

        k_gemm_qkv<<<dim3(DD/128, MB, 3), 256, GEMM_SMEM>>>(p_hconv, wq, wk, wv,
                                                 bq + l*DD, bk + l*DD, bv + l*DD,
                                                 p_q, p_k, p_v);

        k_attn_mma<<<dim3((LL+127)/128, BB*HH), 256, ATT_SMEM>>>(seq_lens, p_ctx);

        k_gemm_mma<0><<<dim3(DD/128, MB), 256, GEMM_SMEM>>>(p_ctx, wo, bo + l*DD, p_t, BLROWS, DD, DD);
        k_addln<<<BLROWS/8, 256>>>(hidden, p_t, ln1_g + l*DD, ln1_b + l*DD);

        k_gemm_mma<1><<<dim3(FFDIM/128, MB), 256, GEMM_SMEM>>>(p_hconv, wi, bi + l*FFDIM, p_ff, BLROWS, FFDIM, DD);
        k_gemm_mma<0><<<dim3(DD/128, MB), 256, GEMM_SMEM>>>(p_ff, wf, bf + l*DD, p_t, BLROWS, DD, FFDIM);
        k_addln<<<BLROWS/8, 256>>>(hidden, p_t, ln2_g + l*DD, ln2_b + l*DD);
    }
}

// round 12
// speedup vs baseline: 1.1277x; 1.0347x over previous
#include <cuda_runtime.h>
#include <cuda_bf16.h>
#include <math.h>

#define BB 32
#define SS 512
#define TT 50
#define LL 562      // S+T
#define DD 512
#define HH 8
#define FFDIM 2048
#define NLAYER 4
#define VBB 30000
#define BLROWS (BB*LL)   // 17984
#define KSPLIT 75
#define KCHUNK 400

// weight-conversion buffer offsets (floats)
#define WQ_OFF 0
#define WK_OFF 1048576
#define WV_OFF 2097152
#define WO_OFF 3145728
#define WI_OFF 4194304
#define WF_OFF 8388608
#define W2_OFF 12582912
#define WCONV_TOTAL 13107200

// ---------------- scratch ----------------
__device__ float g_wd[TT*VBB];
__device__ float g_part[KSPLIT*TT*1024];
__device__ float g_hmem[TT*1024];
__device__ float g_topic[TT*DD];
__device__ float g_q[BLROWS*DD];
__device__ float g_k[BLROWS*DD];
__device__ float g_v[BLROWS*DD];
__device__ float g_ctx[BLROWS*DD];
__device__ float g_t[BLROWS*DD];
__device__ float g_ff[(size_t)BLROWS*FFDIM];
__device__ float g_hconv[BLROWS*DD];
__device__ float g_wconv[WCONV_TOTAL];

// ---------------- helpers ----------------
__device__ __forceinline__ float warp_red_sum(float v){
    #pragma unroll
    for (int o=16;o>0;o>>=1) v += __shfl_xor_sync(0xffffffffu, v, o);
    return v;
}
__device__ __forceinline__ float warp_red_max(float v){
    #pragma unroll
    for (int o=16;o>0;o>>=1) v = fmaxf(v, __shfl_xor_sync(0xffffffffu, v, o));
    return v;
}
__device__ __forceinline__ unsigned f2tf32(float x){
    unsigned r;
    asm("cvt.rna.tf32.f32 %0, %1;" : "=r"(r) : "f"(x));
    return r;
}
__device__ __forceinline__ float rnd_tf32(float x){ return __uint_as_float(f2tf32(x)); }
__device__ __forceinline__ void mma_tf32(float* d, const unsigned* a, unsigned b0, unsigned b1){
    asm volatile(
        "mma.sync.aligned.m16n8k8.row.col.f32.tf32.tf32.f32 "
        "{%0,%1,%2,%3}, {%4,%5,%6,%7}, {%8,%9}, {%0,%1,%2,%3};"
        : "+f"(d[0]), "+f"(d[1]), "+f"(d[2]), "+f"(d[3])
        : "r"(a[0]), "r"(a[1]), "r"(a[2]), "r"(a[3]), "r"(b0), "r"(b1));
}

// tf32-round a tensor (float4 vectorized)
__global__ void k_conv(const float* __restrict__ src, float* __restrict__ dst, int n4){
    int i = blockIdx.x*256 + threadIdx.x;
    if (i >= n4) return;
    float4 v = ((const float4*)src)[i];
    uint4 t; t.x=f2tf32(v.x); t.y=f2tf32(v.y); t.z=f2tf32(v.z); t.w=f2tf32(v.w);
    ((uint4*)dst)[i] = t;
}

// ---------------- topic memory pipeline ----------------
__global__ void k_wdec_softmax(const float* __restrict__ W, const float* __restrict__ bvec){
    int row = blockIdx.x, tid = threadIdx.x;
    __shared__ float red[32];
    const float* w = W + (size_t)row*VBB;
    float m = -1e30f;
    for (int i=tid;i<VBB;i+=1024) m = fmaxf(m, w[i]+bvec[i]);
    m = warp_red_max(m);
    if ((tid&31)==0) red[tid>>5]=m;
    __syncthreads();
    float mm = red[0];
    #pragma unroll
    for (int i=1;i<32;i++) mm = fmaxf(mm, red[i]);
    float s = 0.f;
    for (int i=tid;i<VBB;i+=1024) s += __expf(w[i]+bvec[i]-mm);
    s = warp_red_sum(s);
    __syncthreads();
    if ((tid&31)==0) red[tid>>5]=s;
    __syncthreads();
    float ss = 0.f;
    #pragma unroll
    for (int i=0;i<32;i++) ss += red[i];
    float inv = 1.0f/ss;
    for (int i=tid;i<VBB;i+=1024) g_wd[(size_t)row*VBB+i] = __expf(w[i]+bvec[i]-mm)*inv;
}

__global__ void k_mem_gemm1(const float* __restrict__ W1){
    __shared__ float wds[16][52];
    __shared__ float Ws[16][128];
    int n0 = blockIdx.x*128;
    int k0 = blockIdx.y*KCHUNK;
    int tid = threadIdx.x;
    int n = tid & 127, mb = (tid>>7)*25;
    float acc[25];
    #pragma unroll
    for (int i=0;i<25;i++) acc[i]=0.f;
    for (int kt=0; kt<KCHUNK; kt+=16){
        int kb = k0+kt;
        for (int x=tid;x<800;x+=256){ int m=x>>4, kk=x&15; wds[kk][m]=g_wd[(size_t)m*VBB + kb + kk]; }
        #pragma unroll
        for (int jj=0;jj<2;jj++){
            int idx = tid + jj*256;
            int r = idx>>5, c4 = (idx&31)*4;
            *(float4*)&Ws[r][c4] = *(const float4*)(W1 + (size_t)(kb+r)*1024 + n0 + c4);
        }
        __syncthreads();
        #pragma unroll
        for (int kk=0;kk<16;kk++){
            float w = Ws[kk][n];
            #pragma unroll
            for (int i=0;i<25;i++) acc[i] += wds[kk][mb+i]*w;
        }
        __syncthreads();
    }
    float* out = g_part + (size_t)blockIdx.y*(TT*1024);
    #pragma unroll
    for (int i=0;i<25;i++) out[(mb+i)*1024 + n0 + n] = acc[i];
}

__global__ void k_mem_reduce(const float* __restrict__ b1){
    int i = blockIdx.x*256 + threadIdx.x;
    if (i >= TT*1024) return;
    float s = 0.f;
    for (int ks=0; ks<KSPLIT; ks++) s += g_part[(size_t)ks*(TT*1024) + i];
    s += b1[i & 1023];
    g_hmem[i] = rnd_tf32(fmaxf(s, 0.f));
}

// LN over g_t[50,512] -> g_topic
__global__ __launch_bounds__(512)
void k_ln_topic(const float* __restrict__ src,
                const float* __restrict__ gg, const float* __restrict__ bbv){
    __shared__ float red[16];
    int row = blockIdx.x, tid = threadIdx.x;
    float a = src[row*512+tid];
    float s = warp_red_sum(a);
    if ((tid&31)==0) red[tid>>5]=s;
    __syncthreads();
    float tot=0.f;
    #pragma unroll
    for (int i=0;i<16;i++) tot+=red[i];
    float mean = tot*(1.f/512.f);
    float d = a-mean;
    float q = warp_red_sum(d*d);
    __syncthreads();
    if ((tid&31)==0) red[tid>>5]=q;
    __syncthreads();
    float vq=0.f;
    #pragma unroll
    for (int i=0;i<16;i++) vq+=red[i];
    float inv = rsqrtf(vq*(1.f/512.f) + 1e-12f);
    g_topic[row*512+tid] = d*inv*gg[tid] + bbv[tid];
}

// build hidden into d_out + tf32 copy into g_hconv
__global__ void k_build_hidden(const int* __restrict__ ids, const int* __restrict__ lens_p,
                               const float* __restrict__ embed, float* __restrict__ hid){
    int r = blockIdx.x;
    int b = r / LL, j = r % LL;
    int len = lens_p[b]; len = min(max(len,1),SS);
    const float* src;
    if (j >= len && j < len+TT){
        src = g_topic + (size_t)(j-len)*DD;
    } else {
        int sj = (j < len) ? j : (j - TT);
        sj = min(max(sj,0), SS-1);
        src = embed + (size_t)ids[b*SS + sj]*DD;
    }
    float4 v = ((const float4*)src)[threadIdx.x];
    ((float4*)(hid + (size_t)r*DD))[threadIdx.x] = v;
    uint4 t; t.x=f2tf32(v.x); t.y=f2tf32(v.y); t.z=f2tf32(v.z); t.w=f2tf32(v.w);
    ((uint4*)(g_hconv + (size_t)r*DD))[threadIdx.x] = t;
}

// ---------------- TF32 GEMM: cp.async 2-stage, 2 CTAs/SM ----------------
// operands must already be tf32-rounded.
// ACT: 0 = plain, 1 = gelu + tf32-round output, 2 = tf32-round output
#define AS_F (128*36)            // 4608 floats
#define WS_F (32*136)            // 4352 floats
#define STG_F (AS_F + WS_F)      // 8960 floats = 35840 B / stage
#define GEMM_SMEM (2*STG_F*4)    // 71680 B

template<int ACT>
__device__ __forceinline__
void gemm_cp_body(const float* __restrict__ A, const float* __restrict__ W,
                  const float* __restrict__ bias, float* __restrict__ C,
                  int M, int N, int K, int m0, int n0)
{
    extern __shared__ float sm_[];
    const int tid = threadIdx.x;
    const int lane = tid & 31, warp = tid >> 5;
    const int wm = warp >> 2, wn = warp & 3;
    const int q = lane & 3, g = lane >> 2;

    float acc[4][4][4];
    #pragma unroll
    for (int a=0;a<4;a++)
        #pragma unroll
        for (int b=0;b<4;b++)
            #pragma unroll
            for (int c=0;c<4;c++) acc[a][b][c]=0.f;

    const int am = tid>>3, akv = tid&7;           // A: row am, 16B chunk akv
    const int wk = tid>>5, wnv = tid&31;          // W: row wk, 16B chunk wnv

    { // issue stage 0
        float* As = sm_;
        float* Ws = sm_ + AS_F;
        #pragma unroll
        for (int i=0;i<4;i++){
            int m = am + i*32;
            unsigned dst = (unsigned)__cvta_generic_to_shared(&As[m*36 + akv*4]);
            const float* src = A + (size_t)(m0+m)*K + akv*4;
            int sz = (m0+m < M) ? 16 : 0;
            asm volatile("cp.async.ca.shared.global [%0],[%1],16,%2;\n" :: "r"(dst), "l"(src), "r"(sz));
        }
        #pragma unroll
        for (int i=0;i<4;i++){
            int kk = wk + i*8;
            unsigned dst = (unsigned)__cvta_generic_to_shared(&Ws[kk*136 + wnv*4]);
            const float* src = W + (size_t)kk*N + n0 + wnv*4;
            asm volatile("cp.async.ca.shared.global [%0],[%1],16;\n" :: "r"(dst), "l"(src));
        }
        asm volatile("cp.async.commit_group;\n");
    }

    const int nk = K >> 5;
    for (int kt = 0; kt < nk; kt++){
        asm volatile("cp.async.wait_group 0;\n");
        __syncthreads();
        if (kt+1 < nk){
            int k0 = (kt+1)*32;
            float* As = sm_ + ((kt+1)&1)*STG_F;
            float* Ws = As + AS_F;
            #pragma unroll
            for (int i=0;i<4;i++){
                int m = am + i*32;
                unsigned dst = (unsigned)__cvta_generic_to_shared(&As[m*36 + akv*4]);
                const float* src = A + (size_t)(m0+m)*K + k0 + akv*4;
                int sz = (m0+m < M) ? 16 : 0;
                asm volatile("cp.async.ca.shared.global [%0],[%1],16,%2;\n" :: "r"(dst), "l"(src), "r"(sz));
            }
            #pragma unroll
            for (int i=0;i<4;i++){
                int kk = wk + i*8;
                unsigned dst = (unsigned)__cvta_generic_to_shared(&Ws[kk*136 + wnv*4]);
                const float* src = W + (size_t)(k0+kk)*N + n0 + wnv*4;
                asm volatile("cp.async.ca.shared.global [%0],[%1],16;\n" :: "r"(dst), "l"(src));
            }
            asm volatile("cp.async.commit_group;\n");
        }
        const float* As = sm_ + (kt&1)*STG_F;
        const float* Ws = As + AS_F;
        #pragma unroll
        for (int k8=0;k8<4;k8++){
            unsigned af[4][4], bf[4][2];
            #pragma unroll
            for (int mi=0;mi<4;mi++){
                int mr = wm*64 + mi*16 + g;
                af[mi][0] = __float_as_uint(As[mr*36     + k8*8+q  ]);
                af[mi][1] = __float_as_uint(As[(mr+8)*36 + k8*8+q  ]);
                af[mi][2] = __float_as_uint(As[mr*36     + k8*8+q+4]);
                af[mi][3] = __float_as_uint(As[(mr+8)*36 + k8*8+q+4]);
            }
            #pragma unroll
            for (int nj=0;nj<4;nj++){
                int nc = wn*32 + nj*8 + g;
                bf[nj][0] = __float_as_uint(Ws[(k8*8+q  )*136 + nc]);
                bf[nj][1] = __float_as_uint(Ws[(k8*8+q+4)*136 + nc]);
            }
            #pragma unroll
            for (int mi=0;mi<4;mi++)
                #pragma unroll
                for (int nj=0;nj<4;nj++)
                    mma_tf32(acc[mi][nj], af[mi], bf[nj][0], bf[nj][1]);
        }
    }

    #pragma unroll
    for (int nj=0;nj<4;nj++){
        int c0 = n0 + wn*32 + nj*8 + q*2;
        float bv0 = bias[c0], bv1 = bias[c0+1];
        #pragma unroll
        for (int mi=0;mi<4;mi++){
            int r0 = m0 + wm*64 + mi*16 + g;
            float v0 = acc[mi][nj][0] + bv0;
            float v1 = acc[mi][nj][1] + bv1;
            float v2 = acc[mi][nj][2] + bv0;
            float v3 = acc[mi][nj][3] + bv1;
            if (ACT==1){
                v0 = rnd_tf32(0.5f*v0*(1.0f+erff(v0*0.70710678118654752f)));
                v1 = rnd_tf32(0.5f*v1*(1.0f+erff(v1*0.70710678118654752f)));
                v2 = rnd_tf32(0.5f*v2*(1.0f+erff(v2*0.70710678118654752f)));
                v3 = rnd_tf32(0.5f*v3*(1.0f+erff(v3*0.70710678118654752f)));
            }
            if (ACT==2){
                v0 = rnd_tf32(v0); v1 = rnd_tf32(v1);
                v2 = rnd_tf32(v2); v3 = rnd_tf32(v3);
            }
            if (r0 < M)   { *(float2*)(C + (size_t)r0*N + c0) = make_float2(v0,v1); }
            if (r0+8 < M) { *(float2*)(C + (size_t)(r0+8)*N + c0) = make_float2(v2,v3); }
        }
    }
}

template<int ACT>
__global__ __launch_bounds__(256, 2)
void k_gemm_mma(const float* __restrict__ A, const float* __restrict__ W,
                const float* __restrict__ bias, float* __restrict__ C,
                int M, int N, int K)
{
    gemm_cp_body<ACT>(A, W, bias, C, M, N, K, blockIdx.y*128, blockIdx.x*128);
}

// QKV projection. K/V (z=1,2) blocks whose rows all lie beyond vround = ceil((len+TT)/64)*64
// are never read by attention (KV loop clamped to vround) -> exact early exit.
__global__ __launch_bounds__(256, 2)
void k_gemm_qkv(const float* __restrict__ A, const int* __restrict__ lens_p,
                const float* __restrict__ W0, const float* __restrict__ W1, const float* __restrict__ W2p,
                const float* __restrict__ b0, const float* __restrict__ b1, const float* __restrict__ b2p,
                float* __restrict__ o0, float* __restrict__ o1, float* __restrict__ o2)
{
    if (blockIdx.z != 0){
        int m0 = blockIdx.y*128;
        int bb0 = m0 / LL, bb1 = (m0+127) / LL;
        bool dead = true;
        for (int b = bb0; b <= bb1 && b < BB; b++){
            int lo = max(m0, b*LL) - b*LL;       // smallest j of batch b inside this block
            int len = lens_p[b]; len = min(max(len,1),SS);
            int vr = ((len + TT) + 63) & ~63;    // attention reads rows j < vr
            if (lo < vr) { dead = false; break; }
        }
        if (dead) return;
    }
    const float* W = (blockIdx.z==0) ? W0 : (blockIdx.z==1) ? W1 : W2p;
    const float* bs = (blockIdx.z==0) ? b0 : (blockIdx.z==1) ? b1 : b2p;
    float* C = (blockIdx.z==0) ? o0 : (blockIdx.z==1) ? o1 : o2;
    gemm_cp_body<2>(A, W, bs, C, BLROWS, DD, DD, blockIdx.y*128, blockIdx.x*128);
}

// ---------------- tensor-core flash attention: 128-row Q tile, 8 warps ----------------
// Q/K/V pre-rounded by producer GEMMs.
// KV loop clamped to ceil(valid/64): fully-masked tiles contribute exactly 0.
#define ATT_SMEM ((128*68 + 64*68 + 64*72 + 128*68)*4)   // 105472 B

__global__ __launch_bounds__(256)
void k_attn_mma(const int* __restrict__ lens_p, float* __restrict__ O){
    extern __shared__ float sm[];
    float (*Qs)[68] = (float(*)[68])sm;                                  // 128x68
    float (*Ks)[68] = (float(*)[68])(sm + 128*68);                       // 64x68
    float (*Vs)[72] = (float(*)[72])(sm + 128*68 + 64*68);               // 64x72
    float (*Ps)[68] = (float(*)[68])(sm + 128*68 + 64*68 + 64*72);       // 128x68
    int bh = blockIdx.y;
    int b = bh >> 3, h = bh & 7;
    int q0 = blockIdx.x*128;
    int tid = threadIdx.x, lane = tid&31, w = tid>>5;
    int g = lane>>2, q = lane&3;
    int len = lens_p[b]; len = min(max(len,1),SS);
    int valid = len + TT;
    const float* Qg = g_q + (size_t)b*LL*DD + h*64;
    const float* Kg = g_k + (size_t)b*LL*DD + h*64;
    const float* Vg = g_v + (size_t)b*LL*DD + h*64;

    #pragma unroll
    for (int i=0;i<8;i++){
        int s = tid + i*256;
        int r = s>>4, c4 = (s&15)*4;
        int gr = q0+r;
        float4 v = (gr<LL) ? *(const float4*)(Qg + (size_t)gr*DD + c4) : make_float4(0,0,0,0);
        *(float4*)&Qs[r][c4] = v;
    }
    __syncthreads();
    unsigned qf[8][4];
    {
        int mr = w*16 + g;
        #pragma unroll
        for (int kc=0;kc<8;kc++){
            qf[kc][0]=__float_as_uint(Qs[mr  ][kc*8+q  ]);
            qf[kc][1]=__float_as_uint(Qs[mr+8][kc*8+q  ]);
            qf[kc][2]=__float_as_uint(Qs[mr  ][kc*8+q+4]);
            qf[kc][3]=__float_as_uint(Qs[mr+8][kc*8+q+4]);
        }
    }
    float m0v=-1e30f, m1v=-1e30f, l0=0.f, l1=0.f;
    float oacc[8][4];
    #pragma unroll
    for (int nt=0;nt<8;nt++){ oacc[nt][0]=0.f;oacc[nt][1]=0.f;oacc[nt][2]=0.f;oacc[nt][3]=0.f; }

    const int nkt = (valid + 63) >> 6;
    for (int kt=0; kt<nkt; kt++){
        int k0r = kt*64;
        #pragma unroll
        for (int i=0;i<4;i++){
            int s = tid + i*256;
            int r = s>>4, c4 = (s&15)*4;
            int gr = k0r+r;
            float4 kv4 = (gr<LL) ? *(const float4*)(Kg + (size_t)gr*DD + c4) : make_float4(0,0,0,0);
            float4 vv4 = (gr<LL) ? *(const float4*)(Vg + (size_t)gr*DD + c4) : make_float4(0,0,0,0);
            *(float4*)&Ks[r][c4] = kv4;
            *(float4*)&Vs[r][c4] = vv4;
        }
        __syncthreads();

        float sacc[8][4];
        #pragma unroll
        for (int nt=0;nt<8;nt++){ sacc[nt][0]=0.f;sacc[nt][1]=0.f;sacc[nt][2]=0.f;sacc[nt][3]=0.f; }
        #pragma unroll
        for (int kc=0;kc<8;kc++){
            #pragma unroll
            for (int nt=0;nt<8;nt++){
                unsigned b0 = __float_as_uint(Ks[nt*8+g][kc*8+q  ]);
                unsigned b1 = __float_as_uint(Ks[nt*8+g][kc*8+q+4]);
                mma_tf32(sacc[nt], qf[kc], b0, b1);
            }
        }
        float ml0=-1e30f, ml1=-1e30f;
        #pragma unroll
        for (int nt=0;nt<8;nt++){
            int c = k0r + nt*8 + 2*q;
            float msk0 = (c   >= valid) ? -10000.f : 0.f;
            float msk1 = (c+1 >= valid) ? -10000.f : 0.f;
            sacc[nt][0] = sacc[nt][0]*0.125f + msk0;
            sacc[nt][1] = sacc[nt][1]*0.125f + msk1;
            sacc[nt][2] = sacc[nt][2]*0.125f + msk0;
            sacc[nt][3] = sacc[nt][3]*0.125f + msk1;
            ml0 = fmaxf(ml0, fmaxf(sacc[nt][0], sacc[nt][1]));
            ml1 = fmaxf(ml1, fmaxf(sacc[nt][2], sacc[nt][3]));
        }
        ml0 = fmaxf(ml0, __shfl_xor_sync(0xffffffffu, ml0, 1));
        ml0 = fmaxf(ml0, __shfl_xor_sync(0xffffffffu, ml0, 2));
        ml1 = fmaxf(ml1, __shfl_xor_sync(0xffffffffu, ml1, 1));
        ml1 = fmaxf(ml1, __shfl_xor_sync(0xffffffffu, ml1, 2));
        float mn0 = fmaxf(m0v, ml0), mn1 = fmaxf(m1v, ml1);
        float al0 = __expf(m0v - mn0), al1 = __expf(m1v - mn1);
        m0v = mn0; m1v = mn1;
        float ps0 = 0.f, ps1 = 0.f;
        int mr = w*16 + g;
        #pragma unroll
        for (int nt=0;nt<8;nt++){
            float p0 = __expf(sacc[nt][0]-mn0);
            float p1 = __expf(sacc[nt][1]-mn0);
            float p2 = __expf(sacc[nt][2]-mn1);
            float p3 = __expf(sacc[nt][3]-mn1);
            ps0 += p0+p1; ps1 += p2+p3;
            int pc = nt*8 + 2*q;
            Ps[mr  ][pc]   = rnd_tf32(p0);
            Ps[mr  ][pc+1] = rnd_tf32(p1);
            Ps[mr+8][pc]   = rnd_tf32(p2);
            Ps[mr+8][pc+1] = rnd_tf32(p3);
        }
        ps0 += __shfl_xor_sync(0xffffffffu, ps0, 1);
        ps0 += __shfl_xor_sync(0xffffffffu, ps0, 2);
        ps1 += __shfl_xor_sync(0xffffffffu, ps1, 1);
        ps1 += __shfl_xor_sync(0xffffffffu, ps1, 2);
        l0 = l0*al0 + ps0;
        l1 = l1*al1 + ps1;
        #pragma unroll
        for (int nt=0;nt<8;nt++){
            oacc[nt][0]*=al0; oacc[nt][1]*=al0;
            oacc[nt][2]*=al1; oacc[nt][3]*=al1;
        }
        __syncwarp();
        #pragma unroll
        for (int kc=0;kc<8;kc++){
            unsigned pf[4];
            pf[0]=__float_as_uint(Ps[mr  ][kc*8+q  ]);
            pf[1]=__float_as_uint(Ps[mr+8][kc*8+q  ]);
            pf[2]=__float_as_uint(Ps[mr  ][kc*8+q+4]);
            pf[3]=__float_as_uint(Ps[mr+8][kc*8+q+4]);
            #pragma unroll
            for (int nt=0;nt<8;nt++){
                unsigned b0 = __float_as_uint(Vs[kc*8+q  ][nt*8+g]);
                unsigned b1 = __float_as_uint(Vs[kc*8+q+4][nt*8+g]);
                mma_tf32(oacc[nt], pf, b0, b1);
            }
        }
        __syncthreads();
    }
    float inv0 = 1.f/l0, inv1 = 1.f/l1;
    int r0 = q0 + w*16 + g;
    float* Ob = O + (size_t)b*LL*DD + h*64;
    #pragma unroll
    for (int nt=0;nt<8;nt++){
        int c = nt*8 + 2*q;
        if (r0 < LL)   *(float2*)(Ob + (size_t)r0*DD + c)     = make_float2(rnd_tf32(oacc[nt][0]*inv0), rnd_tf32(oacc[nt][1]*inv0));
        if (r0+8 < LL) *(float2*)(Ob + (size_t)(r0+8)*DD + c) = make_float2(rnd_tf32(oacc[nt][2]*inv1), rnd_tf32(oacc[nt][3]*inv1));
    }
}

// ---------------- residual + LayerNorm (warp per row) + tf32 dual-write ----------------
__global__ __launch_bounds__(256)
void k_addln(float* __restrict__ hid, const float* __restrict__ t,
             const float* __restrict__ gg, const float* __restrict__ bbv){
    int w = threadIdx.x >> 5, lane = threadIdx.x & 31;
    int r = blockIdx.x*8 + w;
    float* hp = hid + (size_t)r*DD;
    const float* tp = t + (size_t)r*DD;
    float4 x[4];
    float s = 0.f;
    #pragma unroll
    for (int i=0;i<4;i++){
        float4 a = *(const float4*)(hp + (lane + i*32)*4);
        float4 c = *(const float4*)(tp + (lane + i*32)*4);
        x[i].x=a.x+c.x; x[i].y=a.y+c.y; x[i].z=a.z+c.z; x[i].w=a.w+c.w;
        s += x[i].x + x[i].y + x[i].z + x[i].w;
    }
    s = warp_red_sum(s);
    float mean = s*(1.f/512.f);
    float q = 0.f;
    #pragma unroll
    for (int i=0;i<4;i++){
        x[i].x-=mean; x[i].y-=mean; x[i].z-=mean; x[i].w-=mean;
        q += x[i].x*x[i].x + x[i].y*x[i].y + x[i].z*x[i].z + x[i].w*x[i].w;
    }
    q = warp_red_sum(q);
    float inv = rsqrtf(q*(1.f/512.f) + 1e-12f);
    float* cp = g_hconv + (size_t)r*DD;
    #pragma unroll
    for (int i=0;i<4;i++){
        float4 gv = *(const float4*)(gg + (lane + i*32)*4);
        float4 bv = *(const float4*)(bbv + (lane + i*32)*4);
        float4 o;
        o.x = x[i].x*inv*gv.x + bv.x;
        o.y = x[i].y*inv*gv.y + bv.y;
        o.z = x[i].z*inv*gv.z + bv.z;
        o.w = x[i].w*inv*gv.w + bv.w;
        *(float4*)(hp + (lane + i*32)*4) = o;
        uint4 tc; tc.x=f2tf32(o.x); tc.y=f2tf32(o.y); tc.z=f2tf32(o.z); tc.w=f2tf32(o.w);
        *(uint4*)(cp + (lane + i*32)*4) = tc;
    }
}

// ---------------- host ----------------
extern "C" void kernel_launch(void* const* d_in, const int* in_sizes, int n_in,
                              void* d_out, int out_size) {
    const int*   input_ids = (const int*)  d_in[0];
    const int*   seq_lens  = (const int*)  d_in[1];
    const float* embed     = (const float*)d_in[2];
    const float* W_dec     = (const float*)d_in[3];
    const float* b_dec     = (const float*)d_in[4];
    const float* mem_W1    = (const float*)d_in[5];
    const float* mem_b1    = (const float*)d_in[6];
    const float* mem_W2    = (const float*)d_in[7];
    const float* mem_b2    = (const float*)d_in[8];
    const float* mem_ln_g  = (const float*)d_in[9];
    const float* mem_ln_b  = (const float*)d_in[10];
    const float* Wq = (const float*)d_in[11];
    const float* bq = (const float*)d_in[12];
    const float* Wk = (const float*)d_in[13];
    const float* bk = (const float*)d_in[14];
    const float* Wv = (const float*)d_in[15];
    const float* bv = (const float*)d_in[16];
    const float* Wo = (const float*)d_in[17];
    const float* bo = (const float*)d_in[18];
    const float* ln1_g = (const float*)d_in[19];
    const float* ln1_b = (const float*)d_in[20];
    const float* Wi = (const float*)d_in[21];
    const float* bi = (const float*)d_in[22];
    const float* Wf = (const float*)d_in[23];
    const float* bf = (const float*)d_in[24];
    const float* ln2_g = (const float*)d_in[25];
    const float* ln2_b = (const float*)d_in[26];

    float* hidden = (float*)d_out;

    float *p_q, *p_k, *p_v, *p_ctx, *p_t, *p_ff, *p_hmem, *p_hconv, *p_wconv;
    cudaGetSymbolAddress((void**)&p_q,   g_q);
    cudaGetSymbolAddress((void**)&p_k,   g_k);
    cudaGetSymbolAddress((void**)&p_v,   g_v);
    cudaGetSymbolAddress((void**)&p_ctx, g_ctx);
    cudaGetSymbolAddress((void**)&p_t,   g_t);
    cudaGetSymbolAddress((void**)&p_ff,  g_ff);
    cudaGetSymbolAddress((void**)&p_hmem, g_hmem);
    cudaGetSymbolAddress((void**)&p_hconv, g_hconv);
    cudaGetSymbolAddress((void**)&p_wconv, g_wconv);

    cudaFuncSetAttribute(k_attn_mma, cudaFuncAttributeMaxDynamicSharedMemorySize, ATT_SMEM);
    cudaFuncSetAttribute(k_gemm_mma<0>, cudaFuncAttributeMaxDynamicSharedMemorySize, GEMM_SMEM);
    cudaFuncSetAttribute(k_gemm_mma<1>, cudaFuncAttributeMaxDynamicSharedMemorySize, GEMM_SMEM);
    cudaFuncSetAttribute(k_gemm_qkv,    cudaFuncAttributeMaxDynamicSharedMemorySize, GEMM_SMEM);

    // one-time weight tf32 conversion (float4)
    k_conv<<<(1048576/4+255)/256, 256>>>(Wq,     p_wconv + WQ_OFF, 1048576/4);
    k_conv<<<(1048576/4+255)/256, 256>>>(Wk,     p_wconv + WK_OFF, 1048576/4);
    k_conv<<<(1048576/4+255)/256, 256>>>(Wv,     p_wconv + WV_OFF, 1048576/4);
    k_conv<<<(1048576/4+255)/256, 256>>>(Wo,     p_wconv + WO_OFF, 1048576/4);
    k_conv<<<(4194304/4+255)/256, 256>>>(Wi,     p_wconv + WI_OFF, 4194304/4);
    k_conv<<<(4194304/4+255)/256, 256>>>(Wf,     p_wconv + WF_OFF, 4194304/4);
    k_conv<<<(524288/4+255)/256, 256>>>(mem_W2, p_wconv + W2_OFF, 524288/4);

    // topic memory
    k_wdec_softmax<<<TT, 1024>>>(W_dec, b_dec);
    k_mem_gemm1<<<dim3(8, KSPLIT), 256>>>(mem_W1);
    k_mem_reduce<<<(TT*1024+255)/256, 256>>>(mem_b1);
    k_gemm_mma<0><<<dim3(4, 1), 256, GEMM_SMEM>>>(p_hmem, p_wconv + W2_OFF, mem_b2, p_t, TT, DD, 1024);
    k_ln_topic<<<TT, 512>>>(p_t, mem_ln_g, mem_ln_b);

    // build hidden into d_out (+ tf32 copy)
    k_build_hidden<<<BLROWS, 128>>>(input_ids, seq_lens, embed, hidden);

    const int MB = (BLROWS + 127)/128;  // 141
    for (int l = 0; l < NLAYER; l++) {
        const float* wq = p_wconv + WQ_OFF + (size_t)l*DD*DD;
        const float* wk = p_wconv + WK_OFF + (size_t)l*DD*DD;
        const float* wv = p_wconv + WV_OFF + (size_t)l*DD*DD;
        const float* wo = p_wconv + WO_OFF + (size_t)l*DD*DD;
        const float* wi = p_wconv + WI_OFF + (size_t)l*DD*FFDIM;
        const float* wf = p_wconv + WF_OFF + (size_t)l*FFDIM*DD;

        k_gemm_qkv<<<dim3(DD/128, MB, 3), 256, GEMM_SMEM>>>(p_hconv, seq_lens, wq, wk, wv,
                                                 bq + l*DD, bk + l*DD, bv + l*DD,
                                                 p_q, p_k, p_v);

        k_attn_mma<<<dim3((LL+127)/128, BB*HH), 256, ATT_SMEM>>>(seq_lens, p_ctx);

        k_gemm_mma<0><<<dim3(DD/128, MB), 256, GEMM_SMEM>>>(p_ctx, wo, bo + l*DD, p_t, BLROWS, DD, DD);
        k_addln<<<BLROWS/8, 256>>>(hidden, p_t, ln1_g + l*DD, ln1_b + l*DD);

        k_gemm_mma<1><<<dim3(FFDIM/128, MB), 256, GEMM_SMEM>>>(p_hconv, wi, bi + l*FFDIM, p_ff, BLROWS, FFDIM, DD);
        k_gemm_mma<0><<<dim3(DD/128, MB), 256, GEMM_SMEM>>>(p_ff, wf, bf + l*DD, p_t, BLROWS, DD, FFDIM);
        k_addln<<<BLROWS/8, 256>>>(hidden, p_t, ln2_g + l*DD, ln2_b + l*DD);
    }
}

// round 13
// speedup vs baseline: 1.1457x; 1.0159x over previous
#include <cuda_runtime.h>
#include <cuda_bf16.h>
#include <math.h>

#define BB 32
#define SS 512
#define TT 50
#define LL 562      // S+T
#define DD 512
#define HH 8
#define FFDIM 2048
#define NLAYER 4
#define VBB 30000
#define BLROWS (BB*LL)   // 17984
#define KSPLIT 75
#define KCHUNK 400

// weight-conversion buffer offsets (floats)
#define WQ_OFF 0
#define WK_OFF 1048576
#define WV_OFF 2097152
#define WO_OFF 3145728
#define WI_OFF 4194304
#define WF_OFF 8388608
#define W2_OFF 12582912
#define WCONV_TOTAL 13107200

// ---------------- scratch ----------------
__device__ float g_wd[TT*VBB];
__device__ float g_part[KSPLIT*TT*1024];
__device__ float g_hmem[TT*1024];
__device__ float g_topic[TT*DD];
__device__ float g_q[BLROWS*DD];
__device__ float g_k[BLROWS*DD];
__device__ float g_v[BLROWS*DD];
__device__ float g_ctx[BLROWS*DD];
__device__ float g_t[BLROWS*DD];
__device__ float g_ff[(size_t)BLROWS*FFDIM];
__device__ float g_hconv[BLROWS*DD];
__device__ float g_wconv[WCONV_TOTAL];

// ---------------- helpers ----------------
__device__ __forceinline__ float warp_red_sum(float v){
    #pragma unroll
    for (int o=16;o>0;o>>=1) v += __shfl_xor_sync(0xffffffffu, v, o);
    return v;
}
__device__ __forceinline__ float warp_red_max(float v){
    #pragma unroll
    for (int o=16;o>0;o>>=1) v = fmaxf(v, __shfl_xor_sync(0xffffffffu, v, o));
    return v;
}
__device__ __forceinline__ unsigned f2tf32(float x){
    unsigned r;
    asm("cvt.rna.tf32.f32 %0, %1;" : "=r"(r) : "f"(x));
    return r;
}
__device__ __forceinline__ float rnd_tf32(float x){ return __uint_as_float(f2tf32(x)); }
__device__ __forceinline__ void mma_tf32(float* d, const unsigned* a, unsigned b0, unsigned b1){
    asm volatile(
        "mma.sync.aligned.m16n8k8.row.col.f32.tf32.tf32.f32 "
        "{%0,%1,%2,%3}, {%4,%5,%6,%7}, {%8,%9}, {%0,%1,%2,%3};"
        : "+f"(d[0]), "+f"(d[1]), "+f"(d[2]), "+f"(d[3])
        : "r"(a[0]), "r"(a[1]), "r"(a[2]), "r"(a[3]), "r"(b0), "r"(b1));
}

// tf32-round a tensor (float4 vectorized)
__global__ void k_conv(const float* __restrict__ src, float* __restrict__ dst, int n4){
    int i = blockIdx.x*256 + threadIdx.x;
    if (i >= n4) return;
    float4 v = ((const float4*)src)[i];
    uint4 t; t.x=f2tf32(v.x); t.y=f2tf32(v.y); t.z=f2tf32(v.z); t.w=f2tf32(v.w);
    ((uint4*)dst)[i] = t;
}

// ---------------- topic memory pipeline ----------------
__global__ void k_wdec_softmax(const float* __restrict__ W, const float* __restrict__ bvec){
    int row = blockIdx.x, tid = threadIdx.x;
    __shared__ float red[32];
    const float* w = W + (size_t)row*VBB;
    float m = -1e30f;
    for (int i=tid;i<VBB;i+=1024) m = fmaxf(m, w[i]+bvec[i]);
    m = warp_red_max(m);
    if ((tid&31)==0) red[tid>>5]=m;
    __syncthreads();
    float mm = red[0];
    #pragma unroll
    for (int i=1;i<32;i++) mm = fmaxf(mm, red[i]);
    float s = 0.f;
    for (int i=tid;i<VBB;i+=1024) s += __expf(w[i]+bvec[i]-mm);
    s = warp_red_sum(s);
    __syncthreads();
    if ((tid&31)==0) red[tid>>5]=s;
    __syncthreads();
    float ss = 0.f;
    #pragma unroll
    for (int i=0;i<32;i++) ss += red[i];
    float inv = 1.0f/ss;
    for (int i=tid;i<VBB;i+=1024) g_wd[(size_t)row*VBB+i] = __expf(w[i]+bvec[i]-mm)*inv;
}

__global__ void k_mem_gemm1(const float* __restrict__ W1){
    __shared__ float wds[16][52];
    __shared__ float Ws[16][128];
    int n0 = blockIdx.x*128;
    int k0 = blockIdx.y*KCHUNK;
    int tid = threadIdx.x;
    int n = tid & 127, mb = (tid>>7)*25;
    float acc[25];
    #pragma unroll
    for (int i=0;i<25;i++) acc[i]=0.f;
    for (int kt=0; kt<KCHUNK; kt+=16){
        int kb = k0+kt;
        for (int x=tid;x<800;x+=256){ int m=x>>4, kk=x&15; wds[kk][m]=g_wd[(size_t)m*VBB + kb + kk]; }
        #pragma unroll
        for (int jj=0;jj<2;jj++){
            int idx = tid + jj*256;
            int r = idx>>5, c4 = (idx&31)*4;
            *(float4*)&Ws[r][c4] = *(const float4*)(W1 + (size_t)(kb+r)*1024 + n0 + c4);
        }
        __syncthreads();
        #pragma unroll
        for (int kk=0;kk<16;kk++){
            float w = Ws[kk][n];
            #pragma unroll
            for (int i=0;i<25;i++) acc[i] += wds[kk][mb+i]*w;
        }
        __syncthreads();
    }
    float* out = g_part + (size_t)blockIdx.y*(TT*1024);
    #pragma unroll
    for (int i=0;i<25;i++) out[(mb+i)*1024 + n0 + n] = acc[i];
}

__global__ void k_mem_reduce(const float* __restrict__ b1){
    int i = blockIdx.x*256 + threadIdx.x;
    if (i >= TT*1024) return;
    float s = 0.f;
    for (int ks=0; ks<KSPLIT; ks++) s += g_part[(size_t)ks*(TT*1024) + i];
    s += b1[i & 1023];
    g_hmem[i] = rnd_tf32(fmaxf(s, 0.f));
}

// LN over g_t[50,512] -> g_topic
__global__ __launch_bounds__(512)
void k_ln_topic(const float* __restrict__ src,
                const float* __restrict__ gg, const float* __restrict__ bbv){
    __shared__ float red[16];
    int row = blockIdx.x, tid = threadIdx.x;
    float a = src[row*512+tid];
    float s = warp_red_sum(a);
    if ((tid&31)==0) red[tid>>5]=s;
    __syncthreads();
    float tot=0.f;
    #pragma unroll
    for (int i=0;i<16;i++) tot+=red[i];
    float mean = tot*(1.f/512.f);
    float d = a-mean;
    float q = warp_red_sum(d*d);
    __syncthreads();
    if ((tid&31)==0) red[tid>>5]=q;
    __syncthreads();
    float vq=0.f;
    #pragma unroll
    for (int i=0;i<16;i++) vq+=red[i];
    float inv = rsqrtf(vq*(1.f/512.f) + 1e-12f);
    g_topic[row*512+tid] = d*inv*gg[tid] + bbv[tid];
}

// build hidden into d_out + tf32 copy into g_hconv
__global__ void k_build_hidden(const int* __restrict__ ids, const int* __restrict__ lens_p,
                               const float* __restrict__ embed, float* __restrict__ hid){
    int r = blockIdx.x;
    int b = r / LL, j = r % LL;
    int len = lens_p[b]; len = min(max(len,1),SS);
    const float* src;
    if (j >= len && j < len+TT){
        src = g_topic + (size_t)(j-len)*DD;
    } else {
        int sj = (j < len) ? j : (j - TT);
        sj = min(max(sj,0), SS-1);
        src = embed + (size_t)ids[b*SS + sj]*DD;
    }
    float4 v = ((const float4*)src)[threadIdx.x];
    ((float4*)(hid + (size_t)r*DD))[threadIdx.x] = v;
    uint4 t; t.x=f2tf32(v.x); t.y=f2tf32(v.y); t.z=f2tf32(v.z); t.w=f2tf32(v.w);
    ((uint4*)(g_hconv + (size_t)r*DD))[threadIdx.x] = t;
}

// ---------------- TF32 GEMM: cp.async 2-stage, 4 warps x (64x64), 2 CTAs/SM ----------------
// operands must already be tf32-rounded.
// ACT: 0 = plain, 1 = gelu + tf32-round output, 2 = tf32-round output
#define AS_F (128*36)            // 4608 floats
#define WS_F (32*136)            // 4352 floats
#define STG_F (AS_F + WS_F)      // 8960 floats = 35840 B / stage
#define GEMM_SMEM (2*STG_F*4)    // 71680 B

template<int ACT>
__device__ __forceinline__
void gemm_cp_body(const float* __restrict__ A, const float* __restrict__ W,
                  const float* __restrict__ bias, float* __restrict__ C,
                  int M, int N, int K, int m0, int n0)
{
    extern __shared__ float sm_[];
    const int tid = threadIdx.x;          // 128 threads, 4 warps
    const int lane = tid & 31, warp = tid >> 5;
    const int wm = warp >> 1, wn = warp & 1;    // 2 x 2 warps, each 64x64
    const int q = lane & 3, g = lane >> 2;

    float acc[4][8][4];
    #pragma unroll
    for (int a=0;a<4;a++)
        #pragma unroll
        for (int b=0;b<8;b++)
            #pragma unroll
            for (int c=0;c<4;c++) acc[a][b][c]=0.f;

    const int am = tid>>3, akv = tid&7;   // A: 16 rows per pass, chunk akv
    const int wk = tid>>5, wnv = tid&31;  // W: 4 rows per pass, chunk wnv

    { // issue stage 0
        float* As = sm_;
        float* Ws = sm_ + AS_F;
        #pragma unroll
        for (int i=0;i<8;i++){
            int m = am + i*16;
            unsigned dst = (unsigned)__cvta_generic_to_shared(&As[m*36 + akv*4]);
            const float* src = A + (size_t)(m0+m)*K + akv*4;
            int sz = (m0+m < M) ? 16 : 0;
            asm volatile("cp.async.ca.shared.global [%0],[%1],16,%2;\n" :: "r"(dst), "l"(src), "r"(sz));
        }
        #pragma unroll
        for (int i=0;i<8;i++){
            int kk = wk + i*4;
            unsigned dst = (unsigned)__cvta_generic_to_shared(&Ws[kk*136 + wnv*4]);
            const float* src = W + (size_t)kk*N + n0 + wnv*4;
            asm volatile("cp.async.ca.shared.global [%0],[%1],16;\n" :: "r"(dst), "l"(src));
        }
        asm volatile("cp.async.commit_group;\n");
    }

    const int nk = K >> 5;
    for (int kt = 0; kt < nk; kt++){
        asm volatile("cp.async.wait_group 0;\n");
        __syncthreads();
        if (kt+1 < nk){
            int k0 = (kt+1)*32;
            float* As = sm_ + ((kt+1)&1)*STG_F;
            float* Ws = As + AS_F;
            #pragma unroll
            for (int i=0;i<8;i++){
                int m = am + i*16;
                unsigned dst = (unsigned)__cvta_generic_to_shared(&As[m*36 + akv*4]);
                const float* src = A + (size_t)(m0+m)*K + k0 + akv*4;
                int sz = (m0+m < M) ? 16 : 0;
                asm volatile("cp.async.ca.shared.global [%0],[%1],16,%2;\n" :: "r"(dst), "l"(src), "r"(sz));
            }
            #pragma unroll
            for (int i=0;i<8;i++){
                int kk = wk + i*4;
                unsigned dst = (unsigned)__cvta_generic_to_shared(&Ws[kk*136 + wnv*4]);
                const float* src = W + (size_t)(k0+kk)*N + n0 + wnv*4;
                asm volatile("cp.async.ca.shared.global [%0],[%1],16;\n" :: "r"(dst), "l"(src));
            }
            asm volatile("cp.async.commit_group;\n");
        }
        const float* As = sm_ + (kt&1)*STG_F;
        const float* Ws = As + AS_F;
        #pragma unroll
        for (int k8=0;k8<4;k8++){
            unsigned af[4][4], bf[8][2];
            #pragma unroll
            for (int mi=0;mi<4;mi++){
                int mr = wm*64 + mi*16 + g;
                af[mi][0] = __float_as_uint(As[mr*36     + k8*8+q  ]);
                af[mi][1] = __float_as_uint(As[(mr+8)*36 + k8*8+q  ]);
                af[mi][2] = __float_as_uint(As[mr*36     + k8*8+q+4]);
                af[mi][3] = __float_as_uint(As[(mr+8)*36 + k8*8+q+4]);
            }
            #pragma unroll
            for (int nj=0;nj<8;nj++){
                int nc = wn*64 + nj*8 + g;
                bf[nj][0] = __float_as_uint(Ws[(k8*8+q  )*136 + nc]);
                bf[nj][1] = __float_as_uint(Ws[(k8*8+q+4)*136 + nc]);
            }
            #pragma unroll
            for (int mi=0;mi<4;mi++)
                #pragma unroll
                for (int nj=0;nj<8;nj++)
                    mma_tf32(acc[mi][nj], af[mi], bf[nj][0], bf[nj][1]);
        }
    }

    #pragma unroll
    for (int nj=0;nj<8;nj++){
        int c0 = n0 + wn*64 + nj*8 + q*2;
        float bv0 = bias[c0], bv1 = bias[c0+1];
        #pragma unroll
        for (int mi=0;mi<4;mi++){
            int r0 = m0 + wm*64 + mi*16 + g;
            float v0 = acc[mi][nj][0] + bv0;
            float v1 = acc[mi][nj][1] + bv1;
            float v2 = acc[mi][nj][2] + bv0;
            float v3 = acc[mi][nj][3] + bv1;
            if (ACT==1){
                v0 = rnd_tf32(0.5f*v0*(1.0f+erff(v0*0.70710678118654752f)));
                v1 = rnd_tf32(0.5f*v1*(1.0f+erff(v1*0.70710678118654752f)));
                v2 = rnd_tf32(0.5f*v2*(1.0f+erff(v2*0.70710678118654752f)));
                v3 = rnd_tf32(0.5f*v3*(1.0f+erff(v3*0.70710678118654752f)));
            }
            if (ACT==2){
                v0 = rnd_tf32(v0); v1 = rnd_tf32(v1);
                v2 = rnd_tf32(v2); v3 = rnd_tf32(v3);
            }
            if (r0 < M)   { *(float2*)(C + (size_t)r0*N + c0) = make_float2(v0,v1); }
            if (r0+8 < M) { *(float2*)(C + (size_t)(r0+8)*N + c0) = make_float2(v2,v3); }
        }
    }
}

template<int ACT>
__global__ __launch_bounds__(128, 2)
void k_gemm_mma(const float* __restrict__ A, const float* __restrict__ W,
                const float* __restrict__ bias, float* __restrict__ C,
                int M, int N, int K)
{
    gemm_cp_body<ACT>(A, W, bias, C, M, N, K, blockIdx.y*128, blockIdx.x*128);
}

// QKV projection. K/V (z=1,2) blocks whose rows all lie beyond vround are dead.
__global__ __launch_bounds__(128, 2)
void k_gemm_qkv(const float* __restrict__ A, const int* __restrict__ lens_p,
                const float* __restrict__ W0, const float* __restrict__ W1, const float* __restrict__ W2p,
                const float* __restrict__ b0, const float* __restrict__ b1, const float* __restrict__ b2p,
                float* __restrict__ o0, float* __restrict__ o1, float* __restrict__ o2)
{
    if (blockIdx.z != 0){
        int m0 = blockIdx.y*128;
        int bb0 = m0 / LL, bb1 = (m0+127) / LL;
        bool dead = true;
        for (int b = bb0; b <= bb1 && b < BB; b++){
            int lo = max(m0, b*LL) - b*LL;
            int len = lens_p[b]; len = min(max(len,1),SS);
            int vr = ((len + TT) + 63) & ~63;
            if (lo < vr) { dead = false; break; }
        }
        if (dead) return;
    }
    const float* W = (blockIdx.z==0) ? W0 : (blockIdx.z==1) ? W1 : W2p;
    const float* bs = (blockIdx.z==0) ? b0 : (blockIdx.z==1) ? b1 : b2p;
    float* C = (blockIdx.z==0) ? o0 : (blockIdx.z==1) ? o1 : o2;
    gemm_cp_body<2>(A, W, bs, C, BLROWS, DD, DD, blockIdx.y*128, blockIdx.x*128);
}

// ---------------- tensor-core flash attention: 128-row Q tile, 8 warps ----------------
#define ATT_SMEM ((128*68 + 64*68 + 64*72 + 128*68)*4)   // 105472 B

__global__ __launch_bounds__(256)
void k_attn_mma(const int* __restrict__ lens_p, float* __restrict__ O){
    extern __shared__ float sm[];
    float (*Qs)[68] = (float(*)[68])sm;
    float (*Ks)[68] = (float(*)[68])(sm + 128*68);
    float (*Vs)[72] = (float(*)[72])(sm + 128*68 + 64*68);
    float (*Ps)[68] = (float(*)[68])(sm + 128*68 + 64*68 + 64*72);
    int bh = blockIdx.y;
    int b = bh >> 3, h = bh & 7;
    int q0 = blockIdx.x*128;
    int tid = threadIdx.x, lane = tid&31, w = tid>>5;
    int g = lane>>2, q = lane&3;
    int len = lens_p[b]; len = min(max(len,1),SS);
    int valid = len + TT;
    const float* Qg = g_q + (size_t)b*LL*DD + h*64;
    const float* Kg = g_k + (size_t)b*LL*DD + h*64;
    const float* Vg = g_v + (size_t)b*LL*DD + h*64;

    #pragma unroll
    for (int i=0;i<8;i++){
        int s = tid + i*256;
        int r = s>>4, c4 = (s&15)*4;
        int gr = q0+r;
        float4 v = (gr<LL) ? *(const float4*)(Qg + (size_t)gr*DD + c4) : make_float4(0,0,0,0);
        *(float4*)&Qs[r][c4] = v;
    }
    __syncthreads();
    unsigned qf[8][4];
    {
        int mr = w*16 + g;
        #pragma unroll
        for (int kc=0;kc<8;kc++){
            qf[kc][0]=__float_as_uint(Qs[mr  ][kc*8+q  ]);
            qf[kc][1]=__float_as_uint(Qs[mr+8][kc*8+q  ]);
            qf[kc][2]=__float_as_uint(Qs[mr  ][kc*8+q+4]);
            qf[kc][3]=__float_as_uint(Qs[mr+8][kc*8+q+4]);
        }
    }
    float m0v=-1e30f, m1v=-1e30f, l0=0.f, l1=0.f;
    float oacc[8][4];
    #pragma unroll
    for (int nt=0;nt<8;nt++){ oacc[nt][0]=0.f;oacc[nt][1]=0.f;oacc[nt][2]=0.f;oacc[nt][3]=0.f; }

    const int nkt = (valid + 63) >> 6;
    for (int kt=0; kt<nkt; kt++){
        int k0r = kt*64;
        #pragma unroll
        for (int i=0;i<4;i++){
            int s = tid + i*256;
            int r = s>>4, c4 = (s&15)*4;
            int gr = k0r+r;
            float4 kv4 = (gr<LL) ? *(const float4*)(Kg + (size_t)gr*DD + c4) : make_float4(0,0,0,0);
            float4 vv4 = (gr<LL) ? *(const float4*)(Vg + (size_t)gr*DD + c4) : make_float4(0,0,0,0);
            *(float4*)&Ks[r][c4] = kv4;
            *(float4*)&Vs[r][c4] = vv4;
        }
        __syncthreads();

        float sacc[8][4];
        #pragma unroll
        for (int nt=0;nt<8;nt++){ sacc[nt][0]=0.f;sacc[nt][1]=0.f;sacc[nt][2]=0.f;sacc[nt][3]=0.f; }
        #pragma unroll
        for (int kc=0;kc<8;kc++){
            #pragma unroll
            for (int nt=0;nt<8;nt++){
                unsigned b0 = __float_as_uint(Ks[nt*8+g][kc*8+q  ]);
                unsigned b1 = __float_as_uint(Ks[nt*8+g][kc*8+q+4]);
                mma_tf32(sacc[nt], qf[kc], b0, b1);
            }
        }
        float ml0=-1e30f, ml1=-1e30f;
        #pragma unroll
        for (int nt=0;nt<8;nt++){
            int c = k0r + nt*8 + 2*q;
            float msk0 = (c   >= valid) ? -10000.f : 0.f;
            float msk1 = (c+1 >= valid) ? -10000.f : 0.f;
            sacc[nt][0] = sacc[nt][0]*0.125f + msk0;
            sacc[nt][1] = sacc[nt][1]*0.125f + msk1;
            sacc[nt][2] = sacc[nt][2]*0.125f + msk0;
            sacc[nt][3] = sacc[nt][3]*0.125f + msk1;
            ml0 = fmaxf(ml0, fmaxf(sacc[nt][0], sacc[nt][1]));
            ml1 = fmaxf(ml1, fmaxf(sacc[nt][2], sacc[nt][3]));
        }
        ml0 = fmaxf(ml0, __shfl_xor_sync(0xffffffffu, ml0, 1));
        ml0 = fmaxf(ml0, __shfl_xor_sync(0xffffffffu, ml0, 2));
        ml1 = fmaxf(ml1, __shfl_xor_sync(0xffffffffu, ml1, 1));
        ml1 = fmaxf(ml1, __shfl_xor_sync(0xffffffffu, ml1, 2));
        float mn0 = fmaxf(m0v, ml0), mn1 = fmaxf(m1v, ml1);
        float al0 = __expf(m0v - mn0), al1 = __expf(m1v - mn1);
        m0v = mn0; m1v = mn1;
        float ps0 = 0.f, ps1 = 0.f;
        int mr = w*16 + g;
        #pragma unroll
        for (int nt=0;nt<8;nt++){
            float p0 = __expf(sacc[nt][0]-mn0);
            float p1 = __expf(sacc[nt][1]-mn0);
            float p2 = __expf(sacc[nt][2]-mn1);
            float p3 = __expf(sacc[nt][3]-mn1);
            ps0 += p0+p1; ps1 += p2+p3;
            int pc = nt*8 + 2*q;
            Ps[mr  ][pc]   = rnd_tf32(p0);
            Ps[mr  ][pc+1] = rnd_tf32(p1);
            Ps[mr+8][pc]   = rnd_tf32(p2);
            Ps[mr+8][pc+1] = rnd_tf32(p3);
        }
        ps0 += __shfl_xor_sync(0xffffffffu, ps0, 1);
        ps0 += __shfl_xor_sync(0xffffffffu, ps0, 2);
        ps1 += __shfl_xor_sync(0xffffffffu, ps1, 1);
        ps1 += __shfl_xor_sync(0xffffffffu, ps1, 2);
        l0 = l0*al0 + ps0;
        l1 = l1*al1 + ps1;
        #pragma unroll
        for (int nt=0;nt<8;nt++){
            oacc[nt][0]*=al0; oacc[nt][1]*=al0;
            oacc[nt][2]*=al1; oacc[nt][3]*=al1;
        }
        __syncwarp();
        #pragma unroll
        for (int kc=0;kc<8;kc++){
            unsigned pf[4];
            pf[0]=__float_as_uint(Ps[mr  ][kc*8+q  ]);
            pf[1]=__float_as_uint(Ps[mr+8][kc*8+q  ]);
            pf[2]=__float_as_uint(Ps[mr  ][kc*8+q+4]);
            pf[3]=__float_as_uint(Ps[mr+8][kc*8+q+4]);
            #pragma unroll
            for (int nt=0;nt<8;nt++){
                unsigned b0 = __float_as_uint(Vs[kc*8+q  ][nt*8+g]);
                unsigned b1 = __float_as_uint(Vs[kc*8+q+4][nt*8+g]);
                mma_tf32(oacc[nt], pf, b0, b1);
            }
        }
        __syncthreads();
    }
    float inv0 = 1.f/l0, inv1 = 1.f/l1;
    int r0 = q0 + w*16 + g;
    float* Ob = O + (size_t)b*LL*DD + h*64;
    #pragma unroll
    for (int nt=0;nt<8;nt++){
        int c = nt*8 + 2*q;
        if (r0 < LL)   *(float2*)(Ob + (size_t)r0*DD + c)     = make_float2(rnd_tf32(oacc[nt][0]*inv0), rnd_tf32(oacc[nt][1]*inv0));
        if (r0+8 < LL) *(float2*)(Ob + (size_t)(r0+8)*DD + c) = make_float2(rnd_tf32(oacc[nt][2]*inv1), rnd_tf32(oacc[nt][3]*inv1));
    }
}

// ---------------- residual + LayerNorm (warp per row) + tf32 dual-write ----------------
__global__ __launch_bounds__(256)
void k_addln(float* __restrict__ hid, const float* __restrict__ t,
             const float* __restrict__ gg, const float* __restrict__ bbv){
    int w = threadIdx.x >> 5, lane = threadIdx.x & 31;
    int r = blockIdx.x*8 + w;
    float* hp = hid + (size_t)r*DD;
    const float* tp = t + (size_t)r*DD;
    float4 x[4];
    float s = 0.f;
    #pragma unroll
    for (int i=0;i<4;i++){
        float4 a = *(const float4*)(hp + (lane + i*32)*4);
        float4 c = *(const float4*)(tp + (lane + i*32)*4);
        x[i].x=a.x+c.x; x[i].y=a.y+c.y; x[i].z=a.z+c.z; x[i].w=a.w+c.w;
        s += x[i].x + x[i].y + x[i].z + x[i].w;
    }
    s = warp_red_sum(s);
    float mean = s*(1.f/512.f);
    float q = 0.f;
    #pragma unroll
    for (int i=0;i<4;i++){
        x[i].x-=mean; x[i].y-=mean; x[i].z-=mean; x[i].w-=mean;
        q += x[i].x*x[i].x + x[i].y*x[i].y + x[i].z*x[i].z + x[i].w*x[i].w;
    }
    q = warp_red_sum(q);
    float inv = rsqrtf(q*(1.f/512.f) + 1e-12f);
    float* cp = g_hconv + (size_t)r*DD;
    #pragma unroll
    for (int i=0;i<4;i++){
        float4 gv = *(const float4*)(gg + (lane + i*32)*4);
        float4 bv = *(const float4*)(bbv + (lane + i*32)*4);
        float4 o;
        o.x = x[i].x*inv*gv.x + bv.x;
        o.y = x[i].y*inv*gv.y + bv.y;
        o.z = x[i].z*inv*gv.z + bv.z;
        o.w = x[i].w*inv*gv.w + bv.w;
        *(float4*)(hp + (lane + i*32)*4) = o;
        uint4 tc; tc.x=f2tf32(o.x); tc.y=f2tf32(o.y); tc.z=f2tf32(o.z); tc.w=f2tf32(o.w);
        *(uint4*)(cp + (lane + i*32)*4) = tc;
    }
}

// ---------------- host ----------------
extern "C" void kernel_launch(void* const* d_in, const int* in_sizes, int n_in,
                              void* d_out, int out_size) {
    const int*   input_ids = (const int*)  d_in[0];
    const int*   seq_lens  = (const int*)  d_in[1];
    const float* embed     = (const float*)d_in[2];
    const float* W_dec     = (const float*)d_in[3];
    const float* b_dec     = (const float*)d_in[4];
    const float* mem_W1    = (const float*)d_in[5];
    const float* mem_b1    = (const float*)d_in[6];
    const float* mem_W2    = (const float*)d_in[7];
    const float* mem_b2    = (const float*)d_in[8];
    const float* mem_ln_g  = (const float*)d_in[9];
    const float* mem_ln_b  = (const float*)d_in[10];
    const float* Wq = (const float*)d_in[11];
    const float* bq = (const float*)d_in[12];
    const float* Wk = (const float*)d_in[13];
    const float* bk = (const float*)d_in[14];
    const float* Wv = (const float*)d_in[15];
    const float* bv = (const float*)d_in[16];
    const float* Wo = (const float*)d_in[17];
    const float* bo = (const float*)d_in[18];
    const float* ln1_g = (const float*)d_in[19];
    const float* ln1_b = (const float*)d_in[20];
    const float* Wi = (const float*)d_in[21];
    const float* bi = (const float*)d_in[22];
    const float* Wf = (const float*)d_in[23];
    const float* bf = (const float*)d_in[24];
    const float* ln2_g = (const float*)d_in[25];
    const float* ln2_b = (const float*)d_in[26];

    float* hidden = (float*)d_out;

    float *p_q, *p_k, *p_v, *p_ctx, *p_t, *p_ff, *p_hmem, *p_hconv, *p_wconv;
    cudaGetSymbolAddress((void**)&p_q,   g_q);
    cudaGetSymbolAddress((void**)&p_k,   g_k);
    cudaGetSymbolAddress((void**)&p_v,   g_v);
    cudaGetSymbolAddress((void**)&p_ctx, g_ctx);
    cudaGetSymbolAddress((void**)&p_t,   g_t);
    cudaGetSymbolAddress((void**)&p_ff,  g_ff);
    cudaGetSymbolAddress((void**)&p_hmem, g_hmem);
    cudaGetSymbolAddress((void**)&p_hconv, g_hconv);
    cudaGetSymbolAddress((void**)&p_wconv, g_wconv);

    cudaFuncSetAttribute(k_attn_mma, cudaFuncAttributeMaxDynamicSharedMemorySize, ATT_SMEM);
    cudaFuncSetAttribute(k_gemm_mma<0>, cudaFuncAttributeMaxDynamicSharedMemorySize, GEMM_SMEM);
    cudaFuncSetAttribute(k_gemm_mma<1>, cudaFuncAttributeMaxDynamicSharedMemorySize, GEMM_SMEM);
    cudaFuncSetAttribute(k_gemm_qkv,    cudaFuncAttributeMaxDynamicSharedMemorySize, GEMM_SMEM);

    // one-time weight tf32 conversion (float4)
    k_conv<<<(1048576/4+255)/256, 256>>>(Wq,     p_wconv + WQ_OFF, 1048576/4);
    k_conv<<<(1048576/4+255)/256, 256>>>(Wk,     p_wconv + WK_OFF, 1048576/4);
    k_conv<<<(1048576/4+255)/256, 256>>>(Wv,     p_wconv + WV_OFF, 1048576/4);
    k_conv<<<(1048576/4+255)/256, 256>>>(Wo,     p_wconv + WO_OFF, 1048576/4);
    k_conv<<<(4194304/4+255)/256, 256>>>(Wi,     p_wconv + WI_OFF, 4194304/4);
    k_conv<<<(4194304/4+255)/256, 256>>>(Wf,     p_wconv + WF_OFF, 4194304/4);
    k_conv<<<(524288/4+255)/256, 256>>>(mem_W2, p_wconv + W2_OFF, 524288/4);

    // topic memory
    k_wdec_softmax<<<TT, 1024>>>(W_dec, b_dec);
    k_mem_gemm1<<<dim3(8, KSPLIT), 256>>>(mem_W1);
    k_mem_reduce<<<(TT*1024+255)/256, 256>>>(mem_b1);
    k_gemm_mma<0><<<dim3(4, 1), 128, GEMM_SMEM>>>(p_hmem, p_wconv + W2_OFF, mem_b2, p_t, TT, DD, 1024);
    k_ln_topic<<<TT, 512>>>(p_t, mem_ln_g, mem_ln_b);

    // build hidden into d_out (+ tf32 copy)
    k_build_hidden<<<BLROWS, 128>>>(input_ids, seq_lens, embed, hidden);

    const int MB = (BLROWS + 127)/128;  // 141
    for (int l = 0; l < NLAYER; l++) {
        const float* wq = p_wconv + WQ_OFF + (size_t)l*DD*DD;
        const float* wk = p_wconv + WK_OFF + (size_t)l*DD*DD;
        const float* wv = p_wconv + WV_OFF + (size_t)l*DD*DD;
        const float* wo = p_wconv + WO_OFF + (size_t)l*DD*DD;
        const float* wi = p_wconv + WI_OFF + (size_t)l*DD*FFDIM;
        const float* wf = p_wconv + WF_OFF + (size_t)l*FFDIM*DD;

        k_gemm_qkv<<<dim3(DD/128, MB, 3), 128, GEMM_SMEM>>>(p_hconv, seq_lens, wq, wk, wv,
                                                 bq + l*DD, bk + l*DD, bv + l*DD,
                                                 p_q, p_k, p_v);

        k_attn_mma<<<dim3((LL+127)/128, BB*HH), 256, ATT_SMEM>>>(seq_lens, p_ctx);

        k_gemm_mma<0><<<dim3(DD/128, MB), 128, GEMM_SMEM>>>(p_ctx, wo, bo + l*DD, p_t, BLROWS, DD, DD);
        k_addln<<<BLROWS/8, 256>>>(hidden, p_t, ln1_g + l*DD, ln1_b + l*DD);

        k_gemm_mma<1><<<dim3(FFDIM/128, MB), 128, GEMM_SMEM>>>(p_hconv, wi, bi + l*FFDIM, p_ff, BLROWS, FFDIM, DD);
        k_gemm_mma<0><<<dim3(DD/128, MB), 128, GEMM_SMEM>>>(p_ff, wf, bf + l*DD, p_t, BLROWS, DD, FFDIM);
        k_addln<<<BLROWS/8, 256>>>(hidden, p_t, ln2_g + l*DD, ln2_b + l*DD);
    }
}